// round 5
// baseline (speedup 1.0000x reference)
#include <cuda_runtime.h>
#include <cuda_bf16.h>
#include <cstdint>

#define Bz 8
#define Cc 512
#define Nn 1024

// ---------------- device scratch (no allocations allowed) --------------------
__device__ float g_yf[Bz*Cc*Nn];               // conv output [B,C,N]
__device__ float g_yn[Bz*Cc*Nn];               // layernorm output [B,C,N]
__device__ float g_q [Bz*Nn*Cc];               // q [B,N,C]
__device__ float g_kv[Bz*Nn*2*Cc];             // kv [B,N,2C] (k | v)
__device__ float g_o [Bz*Nn*Cc];               // attn out [B,N,C]
__device__ float g_attn[(size_t)64*1024*1024]; // attn [64 z][1024 n][1024 m] fp32
__device__ float g_qwT [Cc*Cc];                // q_w^T
__device__ float g_kvwT[Cc*2*Cc];              // kv_w^T
__device__ float g_pwT [Cc*Cc];                // proj_w^T
// bf16 hi/lo split operands for tensor-core GEMMs
__device__ __nv_bfloat16 g_qhi[Bz*Nn*Cc], g_qlo[Bz*Nn*Cc];       // [b,n,512]
__device__ __nv_bfloat16 g_khi[Bz*Nn*Cc], g_klo[Bz*Nn*Cc];       // [b,n,512]
__device__ __nv_bfloat16 g_vthi[(size_t)64*64*1024], g_vtlo[(size_t)64*64*1024]; // [z,d,m]
__device__ __nv_bfloat16 g_chi[(size_t)64*1024*1024], g_clo[(size_t)64*1024*1024]; // [z,n,m]

// =================== warp-MMA helpers (plain sm_103-safe PTX) ================
__device__ __forceinline__ uint32_t smem_u32(const void* p) {
    uint32_t a;
    asm("{ .reg .u64 t; cvta.to.shared.u64 t, %1; cvt.u32.u64 %0, t; }"
        : "=r"(a) : "l"(p));
    return a;
}
__device__ __forceinline__ void ldsm_x4(uint32_t& r0, uint32_t& r1, uint32_t& r2,
                                        uint32_t& r3, uint32_t addr) {
    asm volatile("ldmatrix.sync.aligned.m8n8.x4.shared.b16 {%0,%1,%2,%3}, [%4];"
                 : "=r"(r0), "=r"(r1), "=r"(r2), "=r"(r3) : "r"(addr));
}
__device__ __forceinline__ void ldsm_x2(uint32_t& r0, uint32_t& r1, uint32_t addr) {
    asm volatile("ldmatrix.sync.aligned.m8n8.x2.shared.b16 {%0,%1}, [%2];"
                 : "=r"(r0), "=r"(r1) : "r"(addr));
}
__device__ __forceinline__ void mma_bf16(float* c, const uint32_t* a, const uint32_t* b) {
    asm volatile("mma.sync.aligned.m16n8k16.row.col.f32.bf16.bf16.f32 "
                 "{%0,%1,%2,%3}, {%4,%5,%6,%7}, {%8,%9}, {%0,%1,%2,%3};"
                 : "+f"(c[0]), "+f"(c[1]), "+f"(c[2]), "+f"(c[3])
                 : "r"(a[0]), "r"(a[1]), "r"(a[2]), "r"(a[3]), "r"(b[0]), "r"(b[1]));
}
#define PADB 144   // padded row stride in bytes (72 bf16): conflict-free ldmatrix

// ---------------- kernel 0: 32x32 tiled transpose ----------------------------
__global__ void transpose_kernel(const float* __restrict__ A, float* __restrict__ At,
                                 int R, int C)
{
    __shared__ float tile[32][33];
    int c0 = blockIdx.x * 32, r0 = blockIdx.y * 32;
    int tx = threadIdx.x, ty = threadIdx.y;
    #pragma unroll
    for (int i = ty; i < 32; i += 8)
        tile[i][tx] = A[(size_t)(r0 + i) * C + c0 + tx];
    __syncthreads();
    #pragma unroll
    for (int i = ty; i < 32; i += 8)
        At[(size_t)(c0 + i) * R + r0 + tx] = tile[tx][i];
}

// ---------------- kernel 1: fused multi-scale depthwise conv -----------------
__global__ void conv_kernel(const float* __restrict__ y,
                            const float* __restrict__ w3, const float* __restrict__ b3,
                            const float* __restrict__ w5, const float* __restrict__ b5,
                            const float* __restrict__ w7, const float* __restrict__ b7)
{
    int bc = blockIdx.x;
    int c  = bc & (Cc-1);
    int t  = threadIdx.x;

    __shared__ float tile[38][38];
    __shared__ float wsum[49];
    __shared__ float bias;

    if (t < 49) {
        int dy = t / 7, dx = t % 7;
        float w = w7[c*49 + t];
        if (dy >= 1 && dy <= 5 && dx >= 1 && dx <= 5) w += w5[c*25 + (dy-1)*5 + (dx-1)];
        if (dy >= 2 && dy <= 4 && dx >= 2 && dx <= 4) w += w3[c*9  + (dy-2)*3 + (dx-2)];
        wsum[t] = w;
    }
    if (t == 64) bias = b3[c] + b5[c] + b7[c];

    const float* yp = y + (size_t)bc * Nn;
    for (int i = t; i < 38*38; i += 256) {
        int r  = i / 38 - 3;
        int cl = i % 38 - 3;
        float v = 0.f;
        if (r >= 0 && r < 32 && cl >= 0 && cl < 32) v = yp[r*32 + cl];
        tile[i/38][i%38] = v;
    }
    __syncthreads();

    float* op = g_yf + (size_t)bc * Nn;
    for (int i = t; i < 1024; i += 256) {
        int r = i >> 5, cl = i & 31;
        float acc = bias;
        #pragma unroll
        for (int dy = 0; dy < 7; dy++)
            #pragma unroll
            for (int dx = 0; dx < 7; dx++)
                acc += wsum[dy*7+dx] * tile[r+dy][cl+dx];
        op[i] = acc;
    }
}

// ---------------- kernel 2: layernorm over C per (b,n) -----------------------
__global__ void ln_kernel(const float* __restrict__ lnw, const float* __restrict__ lnb)
{
    int b    = blockIdx.x >> 5;
    int n0   = (blockIdx.x & 31) * 32;
    int lane = threadIdx.x & 31;
    int g    = threadIdx.x >> 5;
    int n    = n0 + lane;

    const float* base = g_yf + (size_t)b*Cc*Nn + n;
    float s = 0.f, s2 = 0.f;
    for (int c = g; c < Cc; c += 8) {
        float v = base[(size_t)c*Nn];
        s += v; s2 += v*v;
    }
    __shared__ float sh[2][8][32];
    sh[0][g][lane] = s; sh[1][g][lane] = s2;
    __syncthreads();
    if (g == 0) {
        float a = 0.f, a2 = 0.f;
        #pragma unroll
        for (int i = 0; i < 8; i++) { a += sh[0][i][lane]; a2 += sh[1][i][lane]; }
        float mu  = a * (1.f/512.f);
        float var = a2 * (1.f/512.f) - mu*mu;
        sh[0][0][lane] = mu;
        sh[1][0][lane] = rsqrtf(var + 1e-5f);
    }
    __syncthreads();
    float mu = sh[0][0][lane], rs = sh[1][0][lane];
    float* ob = g_yn + (size_t)b*Cc*Nn + n;
    for (int c = g; c < Cc; c += 8) {
        float v = base[(size_t)c*Nn];
        ob[(size_t)c*Nn] = (v - mu) * rs * lnw[c] + lnb[c];
    }
}

// ------- kernels 3/4: OUT[b,n,co] = sum_ci Xt[b,ci,n] * Wt[ci,co] -------------
__global__ void __launch_bounds__(256, 2)
gemm_nn_kernel(const float* __restrict__ Xt, const float* __restrict__ Wt,
               float* __restrict__ OUT, int CO)
{
    __shared__ float As[16][128];
    __shared__ float Bs[16][128];
    int co0 = blockIdx.x * 128, n0 = blockIdx.y * 128, b = blockIdx.z;
    int t = threadIdx.x, tx = t & 15, ty = t >> 4;
    const float* Xb = Xt + (size_t)b*Cc*Nn;

    int lr = t >> 4;
    int lc = (t & 15) * 8;

    float acc[8][8] = {};
    for (int k0 = 0; k0 < Cc; k0 += 16) {
        const float* xr = &Xb[(size_t)(k0 + lr)*Nn + n0 + lc];
        const float* wr = &Wt[(size_t)(k0 + lr)*CO + co0 + lc];
        float4 xa = *(const float4*)xr;       float4 xb = *(const float4*)(xr + 4);
        float4 wa = *(const float4*)wr;       float4 wb = *(const float4*)(wr + 4);
        *(float4*)&As[lr][lc] = xa;  *(float4*)&As[lr][lc+4] = xb;
        *(float4*)&Bs[lr][lc] = wa;  *(float4*)&Bs[lr][lc+4] = wb;
        __syncthreads();
        #pragma unroll
        for (int kk = 0; kk < 16; kk++) {
            float a[8], w[8];
            *(float4*)&a[0] = *(const float4*)&As[kk][ty*4];
            *(float4*)&a[4] = *(const float4*)&As[kk][64 + ty*4];
            *(float4*)&w[0] = *(const float4*)&Bs[kk][tx*4];
            *(float4*)&w[4] = *(const float4*)&Bs[kk][64 + tx*4];
            #pragma unroll
            for (int i = 0; i < 8; i++)
                #pragma unroll
                for (int j = 0; j < 8; j++) acc[i][j] += a[i]*w[j];
        }
        __syncthreads();
    }
    #pragma unroll
    for (int i = 0; i < 8; i++) {
        int n = n0 + (i < 4 ? ty*4 + i : 64 + ty*4 + (i-4));
        float* op = &OUT[((size_t)b*Nn + n)*CO + co0];
        *(float4*)&op[tx*4]      = make_float4(acc[i][0],acc[i][1],acc[i][2],acc[i][3]);
        *(float4*)&op[64 + tx*4] = make_float4(acc[i][4],acc[i][5],acc[i][6],acc[i][7]);
    }
}

// ---------- kernel 4b: split q and k into bf16 hi/lo -------------------------
__global__ void split_qk_kernel()
{
    int i4 = blockIdx.x * 256 + threadIdx.x;
    size_t i = (size_t)i4 * 4;
    float4 qv = *(const float4*)&g_q[i];
    int row = i4 >> 7;
    int col4 = i4 & 127;
    float4 kv = *(const float4*)&g_kv[((size_t)row << 10) + col4*4];

    float qa[4] = {qv.x, qv.y, qv.z, qv.w};
    float ka[4] = {kv.x, kv.y, kv.z, kv.w};
    __nv_bfloat16 qh[4], ql[4], kh[4], kl[4];
    #pragma unroll
    for (int j = 0; j < 4; j++) {
        qh[j] = __float2bfloat16(qa[j]);
        ql[j] = __float2bfloat16(qa[j] - __bfloat162float(qh[j]));
        kh[j] = __float2bfloat16(ka[j]);
        kl[j] = __float2bfloat16(ka[j] - __bfloat162float(kh[j]));
    }
    *(uint2*)&g_qhi[i] = *(uint2*)qh;  *(uint2*)&g_qlo[i] = *(uint2*)ql;
    *(uint2*)&g_khi[i] = *(uint2*)kh;  *(uint2*)&g_klo[i] = *(uint2*)kl;
}

// ---------- kernel 4c: v -> transposed bf16 hi/lo  [z][d][m] ------------------
__global__ void split_vt_kernel()
{
    __shared__ float tile[32][33];
    int d0 = blockIdx.x * 32, m0 = blockIdx.y * 32, z = blockIdx.z;
    int b = z >> 3, h = z & 7;
    int tx = threadIdx.x, ty = threadIdx.y;
    #pragma unroll
    for (int i = ty; i < 32; i += 8)
        tile[i][tx] = g_kv[((size_t)(b*Nn + m0 + i))*1024 + 512 + h*64 + d0 + tx];
    __syncthreads();
    #pragma unroll
    for (int i = ty; i < 32; i += 8) {
        float v = tile[tx][i];
        __nv_bfloat16 hi = __float2bfloat16(v);
        __nv_bfloat16 lo = __float2bfloat16(v - __bfloat162float(hi));
        size_t oi = ((size_t)z*64 + d0 + i)*1024 + m0 + tx;
        g_vthi[oi] = hi;  g_vtlo[oi] = lo;
    }
}

// ---------------- kernel 5: QK^T via mma.sync bf16 hi/lo ----------------------
// CTA: 128n x 128m, 8 warps (2n x 4m), warp tile 64n x 32m (4x4 m16n8k16).
#define QK_SMEM (4*128*PADB)     // qhi, qlo, khi, klo: 128 rows x 72 bf16 each
__global__ void __launch_bounds__(256, 1) qk_mma_kernel()
{
    extern __shared__ __align__(16) char sm[];
    const uint32_t QHI = 0, QLO = 128*PADB, KHI = 2*128*PADB, KLO = 3*128*PADB;
    uint32_t sb = smem_u32(sm);

    int t = threadIdx.x, warp = t >> 5, lane = t & 31;
    int m0 = blockIdx.x * 128, n0 = blockIdx.y * 128, z = blockIdx.z;
    int b = z >> 3, h = z & 7;
    int wn = warp >> 2, wm = warp & 3;        // warp grid 2n x 4m

    // ---- load 4 tiles: [128 rows][64 bf16] each, padded rows ----
    {
        const char* srcs[4] = {
            (const char*)(g_qhi + ((size_t)(b*Nn + n0)*Cc + h*64)),
            (const char*)(g_qlo + ((size_t)(b*Nn + n0)*Cc + h*64)),
            (const char*)(g_khi + ((size_t)(b*Nn + m0)*Cc + h*64)),
            (const char*)(g_klo + ((size_t)(b*Nn + m0)*Cc + h*64))};
        const uint32_t offs[4] = {QHI, QLO, KHI, KLO};
        #pragma unroll
        for (int tl = 0; tl < 4; tl++) {
            char* dst = sm + offs[tl];
            for (int i = t; i < 1024; i += 256) {     // 128 rows x 8 x 16B
                int row = i >> 3, cb = (i & 7) * 16;
                *(uint4*)(dst + row*PADB + cb) =
                    *(const uint4*)(srcs[tl] + (size_t)row*(Cc*2) + cb);
            }
        }
    }
    __syncthreads();

    float acc[4][4][4] = {};                   // [mi(n-dir)][ni(m-dir)][4]
    int lr16 = lane & 15, lh = lane >> 4;      // A-frag addressing
    int l8 = lane & 7,  lq = (lane & 15) >> 3; // B-frag addressing

    #pragma unroll
    for (int pass = 0; pass < 3; pass++) {
        uint32_t Abase = sb + (pass == 2 ? QLO : QHI);
        uint32_t Bbase = sb + (pass == 1 ? KLO : KHI);
        uint32_t aAddr = Abase + (wn*64 + lr16)*PADB + lh*16;
        uint32_t bAddr = Bbase + (wm*32 + l8)*PADB + lq*16;
        #pragma unroll
        for (int k0 = 0; k0 < 64; k0 += 16) {
            uint32_t a[4][4], bb[4][2];
            #pragma unroll
            for (int mi = 0; mi < 4; mi++)
                ldsm_x4(a[mi][0], a[mi][1], a[mi][2], a[mi][3],
                        aAddr + mi*16*PADB + k0*2);
            #pragma unroll
            for (int ni = 0; ni < 4; ni++)
                ldsm_x2(bb[ni][0], bb[ni][1], bAddr + ni*8*PADB + k0*2);
            #pragma unroll
            for (int mi = 0; mi < 4; mi++)
                #pragma unroll
                for (int ni = 0; ni < 4; ni++)
                    mma_bf16(acc[mi][ni], a[mi], bb[ni]);
        }
    }

    int rbase = n0 + wn*64 + (lane >> 2);
    int cbase = m0 + wm*32 + (lane & 3)*2;
    #pragma unroll
    for (int mi = 0; mi < 4; mi++)
        #pragma unroll
        for (int ni = 0; ni < 4; ni++) {
            float* c = acc[mi][ni];
            size_t r0i = ((size_t)z*Nn + rbase + mi*16)*Nn + cbase + ni*8;
            *(float2*)&g_attn[r0i]          = make_float2(0.125f*c[0], 0.125f*c[1]);
            *(float2*)&g_attn[r0i + 8*Nn]   = make_float2(0.125f*c[2], 0.125f*c[3]);
        }
}

// ---------------- kernel 6: exact top-k + fused dual softmax -----------------
__device__ __forceinline__ float key2f(unsigned k) {
    unsigned b = (k & 0x80000000u) ? (k ^ 0x80000000u) : ~k;
    return __uint_as_float(b);
}

__device__ __forceinline__ unsigned kth_key(const unsigned* key, int k)
{
    unsigned prefix = 0;
    int kk = k;
    for (int bit = 31; bit >= 0; --bit) {
        unsigned bm = 1u << bit;
        unsigned hi = (bit == 31) ? 0u : (0xFFFFFFFFu << (bit+1));
        int c = 0;
        #pragma unroll
        for (int i = 0; i < 32; i++) {
            unsigned v = key[i];
            c += (((v & hi) == prefix) && (v & bm)) ? 1 : 0;
        }
        c = __reduce_add_sync(0xffffffffu, c);
        if (c == kk) {
            unsigned mn = 0xFFFFFFFFu;
            #pragma unroll
            for (int i = 0; i < 32; i++) {
                unsigned v = key[i];
                if (((v & hi) == prefix) && (v & bm)) mn = min(mn, v);
            }
            return __reduce_min_sync(0xffffffffu, mn);
        } else if (c > kk) {
            prefix |= bm;
        } else {
            kk -= c;
        }
    }
    return prefix;
}

__global__ void select_kernel(const float* __restrict__ kr1, const float* __restrict__ kr2)
{
    int row  = blockIdx.x * 8 + (threadIdx.x >> 5);   // z*1024 + n
    int lane = threadIdx.x & 31;

    float r1 = kr1[0], r2 = kr2[0];
    int k1 = (int)(1024.f * (1.f/(1.f+expf(-r1)))); k1 = min(max(k1,1),1024);
    int k2 = (int)(1024.f * (1.f/(1.f+expf(-r2)))); k2 = min(max(k2,1),1024);

    const float* rp = g_attn + (size_t)row * Nn;
    unsigned key[32];
    #pragma unroll
    for (int i = 0; i < 32; i++) {
        unsigned b = __float_as_uint(rp[i*32 + lane]);
        key[i] = (b & 0x80000000u) ? ~b : (b | 0x80000000u);
    }
    unsigned mx = 0;
    #pragma unroll
    for (int i = 0; i < 32; i++) mx = max(mx, key[i]);
    mx = __reduce_max_sync(0xffffffffu, mx);
    float M = key2f(mx);

    unsigned T1 = kth_key(key, k1);
    unsigned T2 = kth_key(key, k2);

    float s1 = 0.f, s2 = 0.f;
    #pragma unroll
    for (int i = 0; i < 32; i++) {
        float ev = __expf(key2f(key[i]) - M);
        if (key[i] >= T1) s1 += ev;
        if (key[i] >= T2) s2 += ev;
    }
    #pragma unroll
    for (int o = 16; o; o >>= 1) {
        s1 += __shfl_xor_sync(0xffffffffu, s1, o);
        s2 += __shfl_xor_sync(0xffffffffu, s2, o);
    }
    float c1 = 0.6f / s1, c2 = 0.4f / s2;
    __nv_bfloat16* ch = g_chi + (size_t)row * Nn;
    __nv_bfloat16* cl = g_clo + (size_t)row * Nn;
    #pragma unroll
    for (int i = 0; i < 32; i++) {
        float w = (key[i] >= T1 ? c1 : 0.f) + (key[i] >= T2 ? c2 : 0.f);
        float cv = __expf(key2f(key[i]) - M) * w;
        __nv_bfloat16 hi = __float2bfloat16(cv);
        ch[i*32 + lane] = hi;
        cl[i*32 + lane] = __float2bfloat16(cv - __bfloat162float(hi));
    }
}

// ---------------- kernel 7: AV via mma.sync bf16 hi/lo ------------------------
// CTA: 128n x 64d, K=1024 in 16 chunks of 64. 8 warps (4n x 2d),
// warp tile 32n x 32d (2x4 m16n8k16).
#define AV_SMEM (2*128*PADB + 2*64*PADB)
__global__ void __launch_bounds__(256, 1) av_mma_kernel()
{
    extern __shared__ __align__(16) char sm[];
    const uint32_t CHI = 0, CLO = 128*PADB, VHI = 2*128*PADB, VLO = 2*128*PADB + 64*PADB;
    uint32_t sb = smem_u32(sm);

    int t = threadIdx.x, warp = t >> 5, lane = t & 31;
    int n0 = blockIdx.x * 128, z = blockIdx.y;
    int b = z >> 3, h = z & 7;
    int wn = warp >> 1, wd = warp & 1;        // warp grid 4n x 2d

    const char* ch = (const char*)(g_chi  + ((size_t)z*Nn + n0)*Nn);
    const char* cl = (const char*)(g_clo  + ((size_t)z*Nn + n0)*Nn);
    const char* vh = (const char*)(g_vthi + (size_t)z*64*1024);
    const char* vl = (const char*)(g_vtlo + (size_t)z*64*1024);

    float acc[2][4][4] = {};                   // [mi(n)][ni(d)][4]
    int lr16 = lane & 15, lh = lane >> 4;
    int l8 = lane & 7,  lq = (lane & 15) >> 3;

    for (int m0 = 0; m0 < Nn; m0 += 64) {
        for (int i = t; i < 1024; i += 256) {          // coeff hi+lo: 128 rows x 8
            int row = i >> 3, cb = (i & 7) * 16;
            size_t src = (size_t)row*2048 + m0*2 + cb;
            *(uint4*)(sm + CHI + row*PADB + cb) = *(const uint4*)(ch + src);
            *(uint4*)(sm + CLO + row*PADB + cb) = *(const uint4*)(cl + src);
        }
        for (int i = t; i < 512; i += 256) {           // vT hi+lo: 64 rows x 8
            int row = i >> 3, cb = (i & 7) * 16;
            size_t src = (size_t)row*2048 + m0*2 + cb;
            *(uint4*)(sm + VHI + row*PADB + cb) = *(const uint4*)(vh + src);
            *(uint4*)(sm + VLO + row*PADB + cb) = *(const uint4*)(vl + src);
        }
        __syncthreads();

        #pragma unroll
        for (int pass = 0; pass < 3; pass++) {
            uint32_t Abase = sb + (pass == 2 ? CLO : CHI);
            uint32_t Bbase = sb + (pass == 1 ? VLO : VHI);
            uint32_t aAddr = Abase + (wn*32 + lr16)*PADB + lh*16;
            uint32_t bAddr = Bbase + (wd*32 + l8)*PADB + lq*16;
            #pragma unroll
            for (int k0 = 0; k0 < 64; k0 += 16) {
                uint32_t a[2][4], bb[4][2];
                #pragma unroll
                for (int mi = 0; mi < 2; mi++)
                    ldsm_x4(a[mi][0], a[mi][1], a[mi][2], a[mi][3],
                            aAddr + mi*16*PADB + k0*2);
                #pragma unroll
                for (int ni = 0; ni < 4; ni++)
                    ldsm_x2(bb[ni][0], bb[ni][1], bAddr + ni*8*PADB + k0*2);
                #pragma unroll
                for (int mi = 0; mi < 2; mi++)
                    #pragma unroll
                    for (int ni = 0; ni < 4; ni++)
                        mma_bf16(acc[mi][ni], a[mi], bb[ni]);
            }
        }
        __syncthreads();
    }

    int rbase = n0 + wn*32 + (lane >> 2);
    int cbase = h*64 + wd*32 + (lane & 3)*2;
    #pragma unroll
    for (int mi = 0; mi < 2; mi++)
        #pragma unroll
        for (int ni = 0; ni < 4; ni++) {
            float* c = acc[mi][ni];
            size_t o0 = ((size_t)(b*Nn) + rbase + mi*16)*Cc + cbase + ni*8;
            *(float2*)&g_o[o0]        = make_float2(c[0], c[1]);
            *(float2*)&g_o[o0 + 8*Cc] = make_float2(c[2], c[3]);
        }
}

// ------- kernel 8: out[b,c,n] = proj_w[c,:].o[b,n,:] + b[c] + x[b,c,n] --------
__global__ void __launch_bounds__(256, 2)
proj_kernel(const float* __restrict__ Wt, const float* __restrict__ bias,
            const float* __restrict__ x, float* __restrict__ OUT)
{
    __shared__ float As[16][132];
    __shared__ float Bs[16][128];
    int c0 = blockIdx.x * 128, n0 = blockIdx.y * 128, b = blockIdx.z;
    int t = threadIdx.x, tx = t & 15, ty = t >> 4;

    int lr = t >> 1;
    int lk = (t & 1) * 8;
    int wr = t >> 4;
    int wc = (t & 15) * 8;

    float acc[8][8] = {};
    for (int k0 = 0; k0 < Cc; k0 += 16) {
        const float* ar = &g_o[((size_t)b*Nn + n0 + lr)*Cc + k0 + lk];
        float4 a0 = *(const float4*)ar; float4 a1 = *(const float4*)(ar + 4);
        As[lk+0][lr]=a0.x; As[lk+1][lr]=a0.y; As[lk+2][lr]=a0.z; As[lk+3][lr]=a0.w;
        As[lk+4][lr]=a1.x; As[lk+5][lr]=a1.y; As[lk+6][lr]=a1.z; As[lk+7][lr]=a1.w;
        const float* wrp = &Wt[(size_t)(k0 + wr)*Cc + c0 + wc];
        *(float4*)&Bs[wr][wc]   = *(const float4*)wrp;
        *(float4*)&Bs[wr][wc+4] = *(const float4*)(wrp + 4);
        __syncthreads();
        #pragma unroll
        for (int kk = 0; kk < 16; kk++) {
            float a[8], w[8];
            *(float4*)&a[0] = *(const float4*)&As[kk][ty*4];
            *(float4*)&a[4] = *(const float4*)&As[kk][64 + ty*4];
            *(float4*)&w[0] = *(const float4*)&Bs[kk][tx*4];
            *(float4*)&w[4] = *(const float4*)&Bs[kk][64 + tx*4];
            #pragma unroll
            for (int i = 0; i < 8; i++)
                #pragma unroll
                for (int j = 0; j < 8; j++) acc[i][j] += a[i]*w[j];
        }
        __syncthreads();
    }
    #pragma unroll
    for (int j = 0; j < 8; j++) {
        int c = c0 + (j < 4 ? tx*4 + j : 64 + tx*4 + (j-4));
        float bb = bias[c];
        size_t base = ((size_t)b*Cc + c)*Nn;
        int na = n0 + ty*4;
        float4 r0 = *(const float4*)&x[base + na];
        *(float4*)&OUT[base + na] = make_float4(acc[0][j]+bb+r0.x, acc[1][j]+bb+r0.y,
                                                acc[2][j]+bb+r0.z, acc[3][j]+bb+r0.w);
        int nb = n0 + 64 + ty*4;
        float4 r1 = *(const float4*)&x[base + nb];
        *(float4*)&OUT[base + nb] = make_float4(acc[4][j]+bb+r1.x, acc[5][j]+bb+r1.y,
                                                acc[6][j]+bb+r1.z, acc[7][j]+bb+r1.w);
    }
}

// -----------------------------------------------------------------------------
extern "C" void kernel_launch(void* const* d_in, const int* in_sizes, int n_in,
                              void* d_out, int out_size)
{
    const float* x       = (const float*)d_in[0];
    const float* y       = (const float*)d_in[1];
    const float* q_w     = (const float*)d_in[2];
    const float* kv_w    = (const float*)d_in[3];
    const float* proj_w  = (const float*)d_in[4];
    const float* proj_b  = (const float*)d_in[5];
    const float* conv1_w = (const float*)d_in[6];
    const float* conv1_b = (const float*)d_in[7];
    const float* conv2_w = (const float*)d_in[8];
    const float* conv2_b = (const float*)d_in[9];
    const float* conv3_w = (const float*)d_in[10];
    const float* conv3_b = (const float*)d_in[11];
    const float* ln_w    = (const float*)d_in[12];
    const float* ln_b    = (const float*)d_in[13];
    const float* kr1     = (const float*)d_in[14];
    const float* kr2     = (const float*)d_in[15];
    float* out = (float*)d_out;

    float *yn_p, *q_p, *kv_p, *qwT, *kvwT, *pwT;
    cudaGetSymbolAddress((void**)&yn_p, g_yn);
    cudaGetSymbolAddress((void**)&q_p,  g_q);
    cudaGetSymbolAddress((void**)&kv_p, g_kv);
    cudaGetSymbolAddress((void**)&qwT,  g_qwT);
    cudaGetSymbolAddress((void**)&kvwT, g_kvwT);
    cudaGetSymbolAddress((void**)&pwT,  g_pwT);

    cudaFuncSetAttribute(qk_mma_kernel, cudaFuncAttributeMaxDynamicSharedMemorySize, QK_SMEM);
    cudaFuncSetAttribute(av_mma_kernel, cudaFuncAttributeMaxDynamicSharedMemorySize, AV_SMEM);

    dim3 tb(32, 8);
    transpose_kernel<<<dim3(16, 16), tb>>>(q_w,    qwT,  Cc,   Cc);
    transpose_kernel<<<dim3(16, 32), tb>>>(kv_w,   kvwT, 2*Cc, Cc);
    transpose_kernel<<<dim3(16, 16), tb>>>(proj_w, pwT,  Cc,   Cc);

    conv_kernel<<<Bz*Cc, 256>>>(y, conv1_w, conv1_b, conv2_w, conv2_b, conv3_w, conv3_b);
    ln_kernel<<<Bz*32, 256>>>(ln_w, ln_b);

    gemm_nn_kernel<<<dim3(Cc/128,   Nn/128, Bz), 256>>>(x,    qwT,  q_p,  Cc);
    gemm_nn_kernel<<<dim3(2*Cc/128, Nn/128, Bz), 256>>>(yn_p, kvwT, kv_p, 2*Cc);

    split_qk_kernel<<<Bz*Nn*Cc/4/256, 256>>>();
    split_vt_kernel<<<dim3(2, 32, 64), tb>>>();

    qk_mma_kernel<<<dim3(Nn/128, Nn/128, Bz*8), 256, QK_SMEM>>>();
    select_kernel<<<Bz*8*Nn/8, 256>>>(kr1, kr2);
    av_mma_kernel<<<dim3(Nn/128, Bz*8), 256, AV_SMEM>>>();
    proj_kernel<<<dim3(Cc/128, Nn/128, Bz), 256>>>(pwT, proj_b, x, out);
}

// round 6
// speedup vs baseline: 1.2668x; 1.2668x over previous
#include <cuda_runtime.h>
#include <cuda_bf16.h>
#include <cstdint>

#define Bz 8
#define Cc 512
#define Nn 1024

// ---------------- device scratch (no allocations allowed) --------------------
__device__ float g_yf[Bz*Cc*Nn];               // conv output [B,C,N]
__device__ float g_yn[Bz*Cc*Nn];               // layernorm output [B,C,N]
__device__ float g_q [Bz*Nn*Cc];               // q [B,N,C]
__device__ float g_kv[Bz*Nn*2*Cc];             // kv [B,N,2C] (k | v)
__device__ float g_o [Bz*Nn*Cc];               // attn out [B,N,C]
__device__ float g_attn[(size_t)64*1024*1024]; // attn [64 z][1024 n][1024 m] fp32
__device__ float g_qwT [Cc*Cc];                // q_w^T
__device__ float g_kvwT[Cc*2*Cc];              // kv_w^T
__device__ float g_pwT [Cc*Cc];                // proj_w^T
// bf16 operands for tensor-core GEMMs (single precision-pass)
__device__ __nv_bfloat16 g_qhi[Bz*Nn*Cc];                        // [b,n,512]
__device__ __nv_bfloat16 g_khi[Bz*Nn*Cc];                        // [b,n,512]
__device__ __nv_bfloat16 g_vthi[(size_t)64*64*1024];             // [z,d,m]
__device__ __nv_bfloat16 g_chi[(size_t)64*1024*1024];            // [z,n,m]

// =================== warp-MMA helpers (plain sm_103-safe PTX) ================
__device__ __forceinline__ uint32_t smem_u32(const void* p) {
    uint32_t a;
    asm("{ .reg .u64 t; cvta.to.shared.u64 t, %1; cvt.u32.u64 %0, t; }"
        : "=r"(a) : "l"(p));
    return a;
}
__device__ __forceinline__ void ldsm_x4(uint32_t& r0, uint32_t& r1, uint32_t& r2,
                                        uint32_t& r3, uint32_t addr) {
    asm volatile("ldmatrix.sync.aligned.m8n8.x4.shared.b16 {%0,%1,%2,%3}, [%4];"
                 : "=r"(r0), "=r"(r1), "=r"(r2), "=r"(r3) : "r"(addr));
}
__device__ __forceinline__ void ldsm_x2(uint32_t& r0, uint32_t& r1, uint32_t addr) {
    asm volatile("ldmatrix.sync.aligned.m8n8.x2.shared.b16 {%0,%1}, [%2];"
                 : "=r"(r0), "=r"(r1) : "r"(addr));
}
__device__ __forceinline__ void mma_bf16(float* c, const uint32_t* a, const uint32_t* b) {
    asm volatile("mma.sync.aligned.m16n8k16.row.col.f32.bf16.bf16.f32 "
                 "{%0,%1,%2,%3}, {%4,%5,%6,%7}, {%8,%9}, {%0,%1,%2,%3};"
                 : "+f"(c[0]), "+f"(c[1]), "+f"(c[2]), "+f"(c[3])
                 : "r"(a[0]), "r"(a[1]), "r"(a[2]), "r"(a[3]), "r"(b[0]), "r"(b[1]));
}
#define PADB 144   // padded row stride in bytes (72 bf16): conflict-free ldmatrix

// ---------------- kernel 0: 32x32 tiled transpose ----------------------------
__global__ void transpose_kernel(const float* __restrict__ A, float* __restrict__ At,
                                 int R, int C)
{
    __shared__ float tile[32][33];
    int c0 = blockIdx.x * 32, r0 = blockIdx.y * 32;
    int tx = threadIdx.x, ty = threadIdx.y;
    #pragma unroll
    for (int i = ty; i < 32; i += 8)
        tile[i][tx] = A[(size_t)(r0 + i) * C + c0 + tx];
    __syncthreads();
    #pragma unroll
    for (int i = ty; i < 32; i += 8)
        At[(size_t)(c0 + i) * R + r0 + tx] = tile[tx][i];
}

// ---------------- kernel 1: fused multi-scale depthwise conv -----------------
__global__ void conv_kernel(const float* __restrict__ y,
                            const float* __restrict__ w3, const float* __restrict__ b3,
                            const float* __restrict__ w5, const float* __restrict__ b5,
                            const float* __restrict__ w7, const float* __restrict__ b7)
{
    int bc = blockIdx.x;
    int c  = bc & (Cc-1);
    int t  = threadIdx.x;

    __shared__ float tile[38][38];
    __shared__ float wsum[49];
    __shared__ float bias;

    if (t < 49) {
        int dy = t / 7, dx = t % 7;
        float w = w7[c*49 + t];
        if (dy >= 1 && dy <= 5 && dx >= 1 && dx <= 5) w += w5[c*25 + (dy-1)*5 + (dx-1)];
        if (dy >= 2 && dy <= 4 && dx >= 2 && dx <= 4) w += w3[c*9  + (dy-2)*3 + (dx-2)];
        wsum[t] = w;
    }
    if (t == 64) bias = b3[c] + b5[c] + b7[c];

    const float* yp = y + (size_t)bc * Nn;
    for (int i = t; i < 38*38; i += 256) {
        int r  = i / 38 - 3;
        int cl = i % 38 - 3;
        float v = 0.f;
        if (r >= 0 && r < 32 && cl >= 0 && cl < 32) v = yp[r*32 + cl];
        tile[i/38][i%38] = v;
    }
    __syncthreads();

    float* op = g_yf + (size_t)bc * Nn;
    for (int i = t; i < 1024; i += 256) {
        int r = i >> 5, cl = i & 31;
        float acc = bias;
        #pragma unroll
        for (int dy = 0; dy < 7; dy++)
            #pragma unroll
            for (int dx = 0; dx < 7; dx++)
                acc += wsum[dy*7+dx] * tile[r+dy][cl+dx];
        op[i] = acc;
    }
}

// ---------------- kernel 2: layernorm over C per (b,n) -----------------------
__global__ void ln_kernel(const float* __restrict__ lnw, const float* __restrict__ lnb)
{
    int b    = blockIdx.x >> 5;
    int n0   = (blockIdx.x & 31) * 32;
    int lane = threadIdx.x & 31;
    int g    = threadIdx.x >> 5;
    int n    = n0 + lane;

    const float* base = g_yf + (size_t)b*Cc*Nn + n;
    float s = 0.f, s2 = 0.f;
    for (int c = g; c < Cc; c += 8) {
        float v = base[(size_t)c*Nn];
        s += v; s2 += v*v;
    }
    __shared__ float sh[2][8][32];
    sh[0][g][lane] = s; sh[1][g][lane] = s2;
    __syncthreads();
    if (g == 0) {
        float a = 0.f, a2 = 0.f;
        #pragma unroll
        for (int i = 0; i < 8; i++) { a += sh[0][i][lane]; a2 += sh[1][i][lane]; }
        float mu  = a * (1.f/512.f);
        float var = a2 * (1.f/512.f) - mu*mu;
        sh[0][0][lane] = mu;
        sh[1][0][lane] = rsqrtf(var + 1e-5f);
    }
    __syncthreads();
    float mu = sh[0][0][lane], rs = sh[1][0][lane];
    float* ob = g_yn + (size_t)b*Cc*Nn + n;
    for (int c = g; c < Cc; c += 8) {
        float v = base[(size_t)c*Nn];
        ob[(size_t)c*Nn] = (v - mu) * rs * lnw[c] + lnb[c];
    }
}

// ------- kernels 3/4: OUT[b,n,co] = sum_ci Xt[b,ci,n] * Wt[ci,co] -------------
__global__ void __launch_bounds__(256, 2)
gemm_nn_kernel(const float* __restrict__ Xt, const float* __restrict__ Wt,
               float* __restrict__ OUT, int CO)
{
    __shared__ float As[16][128];
    __shared__ float Bs[16][128];
    int co0 = blockIdx.x * 128, n0 = blockIdx.y * 128, b = blockIdx.z;
    int t = threadIdx.x, tx = t & 15, ty = t >> 4;
    const float* Xb = Xt + (size_t)b*Cc*Nn;

    int lr = t >> 4;
    int lc = (t & 15) * 8;

    float acc[8][8] = {};
    for (int k0 = 0; k0 < Cc; k0 += 16) {
        const float* xr = &Xb[(size_t)(k0 + lr)*Nn + n0 + lc];
        const float* wr = &Wt[(size_t)(k0 + lr)*CO + co0 + lc];
        float4 xa = *(const float4*)xr;       float4 xb = *(const float4*)(xr + 4);
        float4 wa = *(const float4*)wr;       float4 wb = *(const float4*)(wr + 4);
        *(float4*)&As[lr][lc] = xa;  *(float4*)&As[lr][lc+4] = xb;
        *(float4*)&Bs[lr][lc] = wa;  *(float4*)&Bs[lr][lc+4] = wb;
        __syncthreads();
        #pragma unroll
        for (int kk = 0; kk < 16; kk++) {
            float a[8], w[8];
            *(float4*)&a[0] = *(const float4*)&As[kk][ty*4];
            *(float4*)&a[4] = *(const float4*)&As[kk][64 + ty*4];
            *(float4*)&w[0] = *(const float4*)&Bs[kk][tx*4];
            *(float4*)&w[4] = *(const float4*)&Bs[kk][64 + tx*4];
            #pragma unroll
            for (int i = 0; i < 8; i++)
                #pragma unroll
                for (int j = 0; j < 8; j++) acc[i][j] += a[i]*w[j];
        }
        __syncthreads();
    }
    #pragma unroll
    for (int i = 0; i < 8; i++) {
        int n = n0 + (i < 4 ? ty*4 + i : 64 + ty*4 + (i-4));
        float* op = &OUT[((size_t)b*Nn + n)*CO + co0];
        *(float4*)&op[tx*4]      = make_float4(acc[i][0],acc[i][1],acc[i][2],acc[i][3]);
        *(float4*)&op[64 + tx*4] = make_float4(acc[i][4],acc[i][5],acc[i][6],acc[i][7]);
    }
}

// ---------- kernel 4b: convert q and k to bf16 --------------------------------
__global__ void split_qk_kernel()
{
    int i4 = blockIdx.x * 256 + threadIdx.x;
    size_t i = (size_t)i4 * 4;
    float4 qv = *(const float4*)&g_q[i];
    int row = i4 >> 7;
    int col4 = i4 & 127;
    float4 kv = *(const float4*)&g_kv[((size_t)row << 10) + col4*4];

    float qa[4] = {qv.x, qv.y, qv.z, qv.w};
    float ka[4] = {kv.x, kv.y, kv.z, kv.w};
    __nv_bfloat16 qh[4], kh[4];
    #pragma unroll
    for (int j = 0; j < 4; j++) {
        qh[j] = __float2bfloat16(qa[j]);
        kh[j] = __float2bfloat16(ka[j]);
    }
    *(uint2*)&g_qhi[i] = *(uint2*)qh;
    *(uint2*)&g_khi[i] = *(uint2*)kh;
}

// ---------- kernel 4c: v -> transposed bf16  [z][d][m] -------------------------
__global__ void split_vt_kernel()
{
    __shared__ float tile[32][33];
    int d0 = blockIdx.x * 32, m0 = blockIdx.y * 32, z = blockIdx.z;
    int b = z >> 3, h = z & 7;
    int tx = threadIdx.x, ty = threadIdx.y;
    #pragma unroll
    for (int i = ty; i < 32; i += 8)
        tile[i][tx] = g_kv[((size_t)(b*Nn + m0 + i))*1024 + 512 + h*64 + d0 + tx];
    __syncthreads();
    #pragma unroll
    for (int i = ty; i < 32; i += 8) {
        float v = tile[tx][i];
        size_t oi = ((size_t)z*64 + d0 + i)*1024 + m0 + tx;
        g_vthi[oi] = __float2bfloat16(v);
    }
}

// ---------------- kernel 5: QK^T via mma.sync bf16 (single pass) --------------
// CTA: 128n x 128m, 8 warps (2n x 4m), warp tile 64n x 32m (4x4 m16n8k16).
#define QK_SMEM (2*128*PADB)     // q, k tiles: 128 rows x 72 bf16 each
__global__ void __launch_bounds__(256, 2) qk_mma_kernel()
{
    extern __shared__ __align__(16) char sm[];
    const uint32_t QT = 0, KT = 128*PADB;
    uint32_t sb = smem_u32(sm);

    int t = threadIdx.x, warp = t >> 5, lane = t & 31;
    int m0 = blockIdx.x * 128, n0 = blockIdx.y * 128, z = blockIdx.z;
    int b = z >> 3, h = z & 7;
    int wn = warp >> 2, wm = warp & 3;        // warp grid 2n x 4m

    // ---- load 2 tiles: [128 rows][64 bf16] each, padded rows ----
    {
        const char* srcs[2] = {
            (const char*)(g_qhi + ((size_t)(b*Nn + n0)*Cc + h*64)),
            (const char*)(g_khi + ((size_t)(b*Nn + m0)*Cc + h*64))};
        const uint32_t offs[2] = {QT, KT};
        #pragma unroll
        for (int tl = 0; tl < 2; tl++) {
            char* dst = sm + offs[tl];
            for (int i = t; i < 1024; i += 256) {     // 128 rows x 8 x 16B
                int row = i >> 3, cb = (i & 7) * 16;
                *(uint4*)(dst + row*PADB + cb) =
                    *(const uint4*)(srcs[tl] + (size_t)row*(Cc*2) + cb);
            }
        }
    }
    __syncthreads();

    float acc[4][4][4] = {};                   // [mi(n-dir)][ni(m-dir)][4]
    int lr16 = lane & 15, lh = lane >> 4;      // A-frag addressing
    int l8 = lane & 7,  lq = (lane & 15) >> 3; // B-frag addressing

    uint32_t aAddr = sb + QT + (wn*64 + lr16)*PADB + lh*16;
    uint32_t bAddr = sb + KT + (wm*32 + l8)*PADB + lq*16;
    #pragma unroll
    for (int k0 = 0; k0 < 64; k0 += 16) {
        uint32_t a[4][4], bb[4][2];
        #pragma unroll
        for (int mi = 0; mi < 4; mi++)
            ldsm_x4(a[mi][0], a[mi][1], a[mi][2], a[mi][3],
                    aAddr + mi*16*PADB + k0*2);
        #pragma unroll
        for (int ni = 0; ni < 4; ni++)
            ldsm_x2(bb[ni][0], bb[ni][1], bAddr + ni*8*PADB + k0*2);
        #pragma unroll
        for (int mi = 0; mi < 4; mi++)
            #pragma unroll
            for (int ni = 0; ni < 4; ni++)
                mma_bf16(acc[mi][ni], a[mi], bb[ni]);
    }

    int rbase = n0 + wn*64 + (lane >> 2);
    int cbase = m0 + wm*32 + (lane & 3)*2;
    #pragma unroll
    for (int mi = 0; mi < 4; mi++)
        #pragma unroll
        for (int ni = 0; ni < 4; ni++) {
            float* c = acc[mi][ni];
            size_t r0i = ((size_t)z*Nn + rbase + mi*16)*Nn + cbase + ni*8;
            *(float2*)&g_attn[r0i]          = make_float2(0.125f*c[0], 0.125f*c[1]);
            *(float2*)&g_attn[r0i + 8*Nn]   = make_float2(0.125f*c[2], 0.125f*c[3]);
        }
}

// ---------------- kernel 6: exact top-k + fused dual softmax -----------------
__device__ __forceinline__ float key2f(unsigned k) {
    unsigned b = (k & 0x80000000u) ? (k ^ 0x80000000u) : ~k;
    return __uint_as_float(b);
}

__device__ __forceinline__ unsigned kth_key(const unsigned* key, int k)
{
    unsigned prefix = 0;
    int kk = k;
    for (int bit = 31; bit >= 0; --bit) {
        unsigned bm = 1u << bit;
        unsigned hi = (bit == 31) ? 0u : (0xFFFFFFFFu << (bit+1));
        int c = 0;
        #pragma unroll
        for (int i = 0; i < 32; i++) {
            unsigned v = key[i];
            c += (((v & hi) == prefix) && (v & bm)) ? 1 : 0;
        }
        c = __reduce_add_sync(0xffffffffu, c);
        if (c == kk) {
            unsigned mn = 0xFFFFFFFFu;
            #pragma unroll
            for (int i = 0; i < 32; i++) {
                unsigned v = key[i];
                if (((v & hi) == prefix) && (v & bm)) mn = min(mn, v);
            }
            return __reduce_min_sync(0xffffffffu, mn);
        } else if (c > kk) {
            prefix |= bm;
        } else {
            kk -= c;
        }
    }
    return prefix;
}

__global__ void select_kernel(const float* __restrict__ kr1, const float* __restrict__ kr2)
{
    int row  = blockIdx.x * 8 + (threadIdx.x >> 5);   // z*1024 + n
    int lane = threadIdx.x & 31;

    float r1 = kr1[0], r2 = kr2[0];
    int k1 = (int)(1024.f * (1.f/(1.f+expf(-r1)))); k1 = min(max(k1,1),1024);
    int k2 = (int)(1024.f * (1.f/(1.f+expf(-r2)))); k2 = min(max(k2,1),1024);

    const float* rp = g_attn + (size_t)row * Nn;
    unsigned key[32];
    #pragma unroll
    for (int i = 0; i < 32; i++) {
        unsigned b = __float_as_uint(rp[i*32 + lane]);
        key[i] = (b & 0x80000000u) ? ~b : (b | 0x80000000u);
    }
    unsigned mx = 0;
    #pragma unroll
    for (int i = 0; i < 32; i++) mx = max(mx, key[i]);
    mx = __reduce_max_sync(0xffffffffu, mx);
    float M = key2f(mx);

    unsigned T1 = kth_key(key, k1);
    unsigned T2 = kth_key(key, k2);

    float s1 = 0.f, s2 = 0.f;
    #pragma unroll
    for (int i = 0; i < 32; i++) {
        float ev = __expf(key2f(key[i]) - M);
        if (key[i] >= T1) s1 += ev;
        if (key[i] >= T2) s2 += ev;
    }
    #pragma unroll
    for (int o = 16; o; o >>= 1) {
        s1 += __shfl_xor_sync(0xffffffffu, s1, o);
        s2 += __shfl_xor_sync(0xffffffffu, s2, o);
    }
    float c1 = 0.6f / s1, c2 = 0.4f / s2;
    __nv_bfloat16* ch = g_chi + (size_t)row * Nn;
    #pragma unroll
    for (int i = 0; i < 32; i++) {
        float w = (key[i] >= T1 ? c1 : 0.f) + (key[i] >= T2 ? c2 : 0.f);
        float cv = __expf(key2f(key[i]) - M) * w;
        ch[i*32 + lane] = __float2bfloat16(cv);
    }
}

// ---------------- kernel 7: AV via mma.sync bf16 (single pass) ----------------
// CTA: 128n x 64d, K=1024 in 16 chunks of 64. 8 warps (4n x 2d),
// warp tile 32n x 32d (2x4 m16n8k16).
#define AV_SMEM (128*PADB + 64*PADB)
__global__ void __launch_bounds__(256, 2) av_mma_kernel()
{
    extern __shared__ __align__(16) char sm[];
    const uint32_t CT = 0, VT = 128*PADB;
    uint32_t sb = smem_u32(sm);

    int t = threadIdx.x, warp = t >> 5, lane = t & 31;
    int n0 = blockIdx.x * 128, z = blockIdx.y;
    int b = z >> 3, h = z & 7;
    int wn = warp >> 1, wd = warp & 1;        // warp grid 4n x 2d

    const char* ch = (const char*)(g_chi  + ((size_t)z*Nn + n0)*Nn);
    const char* vh = (const char*)(g_vthi + (size_t)z*64*1024);

    float acc[2][4][4] = {};                   // [mi(n)][ni(d)][4]
    int lr16 = lane & 15, lh = lane >> 4;
    int l8 = lane & 7,  lq = (lane & 15) >> 3;

    for (int m0 = 0; m0 < Nn; m0 += 64) {
        for (int i = t; i < 1024; i += 256) {          // coeff: 128 rows x 8
            int row = i >> 3, cb = (i & 7) * 16;
            size_t src = (size_t)row*2048 + m0*2 + cb;
            *(uint4*)(sm + CT + row*PADB + cb) = *(const uint4*)(ch + src);
        }
        for (int i = t; i < 512; i += 256) {           // vT: 64 rows x 8
            int row = i >> 3, cb = (i & 7) * 16;
            size_t src = (size_t)row*2048 + m0*2 + cb;
            *(uint4*)(sm + VT + row*PADB + cb) = *(const uint4*)(vh + src);
        }
        __syncthreads();

        uint32_t aAddr = sb + CT + (wn*32 + lr16)*PADB + lh*16;
        uint32_t bAddr = sb + VT + (wd*32 + l8)*PADB + lq*16;
        #pragma unroll
        for (int k0 = 0; k0 < 64; k0 += 16) {
            uint32_t a[2][4], bb[4][2];
            #pragma unroll
            for (int mi = 0; mi < 2; mi++)
                ldsm_x4(a[mi][0], a[mi][1], a[mi][2], a[mi][3],
                        aAddr + mi*16*PADB + k0*2);
            #pragma unroll
            for (int ni = 0; ni < 4; ni++)
                ldsm_x2(bb[ni][0], bb[ni][1], bAddr + ni*8*PADB + k0*2);
            #pragma unroll
            for (int mi = 0; mi < 2; mi++)
                #pragma unroll
                for (int ni = 0; ni < 4; ni++)
                    mma_bf16(acc[mi][ni], a[mi], bb[ni]);
        }
        __syncthreads();
    }

    int rbase = n0 + wn*32 + (lane >> 2);
    int cbase = h*64 + wd*32 + (lane & 3)*2;
    #pragma unroll
    for (int mi = 0; mi < 2; mi++)
        #pragma unroll
        for (int ni = 0; ni < 4; ni++) {
            float* c = acc[mi][ni];
            size_t o0 = ((size_t)(b*Nn) + rbase + mi*16)*Cc + cbase + ni*8;
            *(float2*)&g_o[o0]        = make_float2(c[0], c[1]);
            *(float2*)&g_o[o0 + 8*Cc] = make_float2(c[2], c[3]);
        }
}

// ------- kernel 8: out[b,c,n] = proj_w[c,:].o[b,n,:] + b[c] + x[b,c,n] --------
__global__ void __launch_bounds__(256, 2)
proj_kernel(const float* __restrict__ Wt, const float* __restrict__ bias,
            const float* __restrict__ x, float* __restrict__ OUT)
{
    __shared__ float As[16][132];
    __shared__ float Bs[16][128];
    int c0 = blockIdx.x * 128, n0 = blockIdx.y * 128, b = blockIdx.z;
    int t = threadIdx.x, tx = t & 15, ty = t >> 4;

    int lr = t >> 1;
    int lk = (t & 1) * 8;
    int wr = t >> 4;
    int wc = (t & 15) * 8;

    float acc[8][8] = {};
    for (int k0 = 0; k0 < Cc; k0 += 16) {
        const float* ar = &g_o[((size_t)b*Nn + n0 + lr)*Cc + k0 + lk];
        float4 a0 = *(const float4*)ar; float4 a1 = *(const float4*)(ar + 4);
        As[lk+0][lr]=a0.x; As[lk+1][lr]=a0.y; As[lk+2][lr]=a0.z; As[lk+3][lr]=a0.w;
        As[lk+4][lr]=a1.x; As[lk+5][lr]=a1.y; As[lk+6][lr]=a1.z; As[lk+7][lr]=a1.w;
        const float* wrp = &Wt[(size_t)(k0 + wr)*Cc + c0 + wc];
        *(float4*)&Bs[wr][wc]   = *(const float4*)wrp;
        *(float4*)&Bs[wr][wc+4] = *(const float4*)(wrp + 4);
        __syncthreads();
        #pragma unroll
        for (int kk = 0; kk < 16; kk++) {
            float a[8], w[8];
            *(float4*)&a[0] = *(const float4*)&As[kk][ty*4];
            *(float4*)&a[4] = *(const float4*)&As[kk][64 + ty*4];
            *(float4*)&w[0] = *(const float4*)&Bs[kk][tx*4];
            *(float4*)&w[4] = *(const float4*)&Bs[kk][64 + tx*4];
            #pragma unroll
            for (int i = 0; i < 8; i++)
                #pragma unroll
                for (int j = 0; j < 8; j++) acc[i][j] += a[i]*w[j];
        }
        __syncthreads();
    }
    #pragma unroll
    for (int j = 0; j < 8; j++) {
        int c = c0 + (j < 4 ? tx*4 + j : 64 + tx*4 + (j-4));
        float bb = bias[c];
        size_t base = ((size_t)b*Cc + c)*Nn;
        int na = n0 + ty*4;
        float4 r0 = *(const float4*)&x[base + na];
        *(float4*)&OUT[base + na] = make_float4(acc[0][j]+bb+r0.x, acc[1][j]+bb+r0.y,
                                                acc[2][j]+bb+r0.z, acc[3][j]+bb+r0.w);
        int nb = n0 + 64 + ty*4;
        float4 r1 = *(const float4*)&x[base + nb];
        *(float4*)&OUT[base + nb] = make_float4(acc[4][j]+bb+r1.x, acc[5][j]+bb+r1.y,
                                                acc[6][j]+bb+r1.z, acc[7][j]+bb+r1.w);
    }
}

// -----------------------------------------------------------------------------
extern "C" void kernel_launch(void* const* d_in, const int* in_sizes, int n_in,
                              void* d_out, int out_size)
{
    const float* x       = (const float*)d_in[0];
    const float* y       = (const float*)d_in[1];
    const float* q_w     = (const float*)d_in[2];
    const float* kv_w    = (const float*)d_in[3];
    const float* proj_w  = (const float*)d_in[4];
    const float* proj_b  = (const float*)d_in[5];
    const float* conv1_w = (const float*)d_in[6];
    const float* conv1_b = (const float*)d_in[7];
    const float* conv2_w = (const float*)d_in[8];
    const float* conv2_b = (const float*)d_in[9];
    const float* conv3_w = (const float*)d_in[10];
    const float* conv3_b = (const float*)d_in[11];
    const float* ln_w    = (const float*)d_in[12];
    const float* ln_b    = (const float*)d_in[13];
    const float* kr1     = (const float*)d_in[14];
    const float* kr2     = (const float*)d_in[15];
    float* out = (float*)d_out;

    float *yn_p, *q_p, *kv_p, *qwT, *kvwT, *pwT;
    cudaGetSymbolAddress((void**)&yn_p, g_yn);
    cudaGetSymbolAddress((void**)&q_p,  g_q);
    cudaGetSymbolAddress((void**)&kv_p, g_kv);
    cudaGetSymbolAddress((void**)&qwT,  g_qwT);
    cudaGetSymbolAddress((void**)&kvwT, g_kvwT);
    cudaGetSymbolAddress((void**)&pwT,  g_pwT);

    cudaFuncSetAttribute(qk_mma_kernel, cudaFuncAttributeMaxDynamicSharedMemorySize, QK_SMEM);
    cudaFuncSetAttribute(av_mma_kernel, cudaFuncAttributeMaxDynamicSharedMemorySize, AV_SMEM);

    dim3 tb(32, 8);
    transpose_kernel<<<dim3(16, 16), tb>>>(q_w,    qwT,  Cc,   Cc);
    transpose_kernel<<<dim3(16, 32), tb>>>(kv_w,   kvwT, 2*Cc, Cc);
    transpose_kernel<<<dim3(16, 16), tb>>>(proj_w, pwT,  Cc,   Cc);

    conv_kernel<<<Bz*Cc, 256>>>(y, conv1_w, conv1_b, conv2_w, conv2_b, conv3_w, conv3_b);
    ln_kernel<<<Bz*32, 256>>>(ln_w, ln_b);

    gemm_nn_kernel<<<dim3(Cc/128,   Nn/128, Bz), 256>>>(x,    qwT,  q_p,  Cc);
    gemm_nn_kernel<<<dim3(2*Cc/128, Nn/128, Bz), 256>>>(yn_p, kvwT, kv_p, 2*Cc);

    split_qk_kernel<<<Bz*Nn*Cc/4/256, 256>>>();
    split_vt_kernel<<<dim3(2, 32, 64), tb>>>();

    qk_mma_kernel<<<dim3(Nn/128, Nn/128, Bz*8), 256, QK_SMEM>>>();
    select_kernel<<<Bz*8*Nn/8, 256>>>(kr1, kr2);
    av_mma_kernel<<<dim3(Nn/128, Bz*8), 256, AV_SMEM>>>();
    proj_kernel<<<dim3(Cc/128, Nn/128, Bz), 256>>>(pwT, proj_b, x, out);
}

// round 7
// speedup vs baseline: 1.5285x; 1.2066x over previous
#include <cuda_runtime.h>
#include <cuda_bf16.h>
#include <cstdint>

#define Bz 8
#define Cc 512
#define Nn 1024

// ---------------- device scratch (no allocations allowed) --------------------
__device__ float g_yf[Bz*Cc*Nn];               // conv output [B,C,N]
__device__ float g_yn[Bz*Cc*Nn];               // layernorm output [B,C,N]
__device__ float g_o [Bz*Nn*Cc];               // attn out [B,N,C]
__device__ float g_attn[(size_t)64*1024*1024]; // attn [64 z][1024 n][1024 m] fp32
__device__ float g_pwT [Cc*Cc];                // proj_w^T (fp32)
// bf16 operand buffers
__device__ __nv_bfloat16 g_xbf [Bz*Nn*Cc];     // x^T  [b,n,512]
__device__ __nv_bfloat16 g_ynbf[Bz*Nn*Cc];     // yn^T [b,n,512]
__device__ __nv_bfloat16 g_qwb [Cc*Cc];        // q_w  [co,512]
__device__ __nv_bfloat16 g_kvwb[2*Cc*Cc];      // kv_w [co,512]
__device__ __nv_bfloat16 g_qbf [Bz*Nn*Cc];     // q  [b,n,512]
__device__ __nv_bfloat16 g_kbf [Bz*Nn*Cc];     // k  [b,n,512]
__device__ __nv_bfloat16 g_vbf [Bz*Nn*Cc];     // v  [b,n,512]
__device__ __nv_bfloat16 g_vthi[(size_t)64*64*1024];   // v^T [z,d,m]
__device__ __nv_bfloat16 g_chi [(size_t)64*1024*1024]; // coeff [z,n,m]

// =================== warp-MMA helpers (plain sm_103-safe PTX) ================
__device__ __forceinline__ uint32_t smem_u32(const void* p) {
    uint32_t a;
    asm("{ .reg .u64 t; cvta.to.shared.u64 t, %1; cvt.u32.u64 %0, t; }"
        : "=r"(a) : "l"(p));
    return a;
}
__device__ __forceinline__ void ldsm_x4(uint32_t& r0, uint32_t& r1, uint32_t& r2,
                                        uint32_t& r3, uint32_t addr) {
    asm volatile("ldmatrix.sync.aligned.m8n8.x4.shared.b16 {%0,%1,%2,%3}, [%4];"
                 : "=r"(r0), "=r"(r1), "=r"(r2), "=r"(r3) : "r"(addr));
}
__device__ __forceinline__ void ldsm_x2(uint32_t& r0, uint32_t& r1, uint32_t addr) {
    asm volatile("ldmatrix.sync.aligned.m8n8.x2.shared.b16 {%0,%1}, [%2];"
                 : "=r"(r0), "=r"(r1) : "r"(addr));
}
__device__ __forceinline__ void mma_bf16(float* c, const uint32_t* a, const uint32_t* b) {
    asm volatile("mma.sync.aligned.m16n8k16.row.col.f32.bf16.bf16.f32 "
                 "{%0,%1,%2,%3}, {%4,%5,%6,%7}, {%8,%9}, {%0,%1,%2,%3};"
                 : "+f"(c[0]), "+f"(c[1]), "+f"(c[2]), "+f"(c[3])
                 : "r"(a[0]), "r"(a[1]), "r"(a[2]), "r"(a[3]), "r"(b[0]), "r"(b[1]));
}
#define PADB 144   // padded row stride in bytes (72 bf16): conflict-free ldmatrix

// ---------------- kernel 0a: 32x32 tiled transpose (fp32, for proj_w) --------
__global__ void transpose_kernel(const float* __restrict__ A, float* __restrict__ At,
                                 int R, int C)
{
    __shared__ float tile[32][33];
    int c0 = blockIdx.x * 32, r0 = blockIdx.y * 32;
    int tx = threadIdx.x, ty = threadIdx.y;
    #pragma unroll
    for (int i = ty; i < 32; i += 8)
        tile[i][tx] = A[(size_t)(r0 + i) * C + c0 + tx];
    __syncthreads();
    #pragma unroll
    for (int i = ty; i < 32; i += 8)
        At[(size_t)(c0 + i) * R + r0 + tx] = tile[tx][i];
}

// ---------------- kernel 0b: fp32 -> bf16 elementwise (weights) --------------
__global__ void wcvt_kernel(const float* __restrict__ S, __nv_bfloat16* __restrict__ D)
{
    int i4 = blockIdx.x * 256 + threadIdx.x;
    float4 v = *(const float4*)&S[(size_t)i4 * 4];
    __nv_bfloat16 o[4] = {__float2bfloat16(v.x), __float2bfloat16(v.y),
                          __float2bfloat16(v.z), __float2bfloat16(v.w)};
    *(uint2*)&D[(size_t)i4 * 4] = *(uint2*)o;
}

// ------- kernel 0c: [B,C,N] fp32 -> [B,N,C] bf16 transpose-convert -----------
__global__ void tcvt_kernel(const float* __restrict__ S, __nv_bfloat16* __restrict__ D)
{
    __shared__ float tile[32][33];
    int n0 = blockIdx.x * 32, c0 = blockIdx.y * 32, b = blockIdx.z;
    int tx = threadIdx.x, ty = threadIdx.y;
    #pragma unroll
    for (int i = ty; i < 32; i += 8)
        tile[i][tx] = S[((size_t)b*Cc + c0 + i)*Nn + n0 + tx];
    __syncthreads();
    #pragma unroll
    for (int i = ty; i < 32; i += 8)
        D[((size_t)b*Nn + n0 + i)*Cc + c0 + tx] = __float2bfloat16(tile[tx][i]);
}

// ---------------- kernel 1: fused multi-scale depthwise conv -----------------
__global__ void conv_kernel(const float* __restrict__ y,
                            const float* __restrict__ w3, const float* __restrict__ b3,
                            const float* __restrict__ w5, const float* __restrict__ b5,
                            const float* __restrict__ w7, const float* __restrict__ b7)
{
    int bc = blockIdx.x;
    int c  = bc & (Cc-1);
    int t  = threadIdx.x;

    __shared__ float tile[38][38];
    __shared__ float wsum[49];
    __shared__ float bias;

    if (t < 49) {
        int dy = t / 7, dx = t % 7;
        float w = w7[c*49 + t];
        if (dy >= 1 && dy <= 5 && dx >= 1 && dx <= 5) w += w5[c*25 + (dy-1)*5 + (dx-1)];
        if (dy >= 2 && dy <= 4 && dx >= 2 && dx <= 4) w += w3[c*9  + (dy-2)*3 + (dx-2)];
        wsum[t] = w;
    }
    if (t == 64) bias = b3[c] + b5[c] + b7[c];

    const float* yp = y + (size_t)bc * Nn;
    for (int i = t; i < 38*38; i += 256) {
        int r  = i / 38 - 3;
        int cl = i % 38 - 3;
        float v = 0.f;
        if (r >= 0 && r < 32 && cl >= 0 && cl < 32) v = yp[r*32 + cl];
        tile[i/38][i%38] = v;
    }
    __syncthreads();

    float* op = g_yf + (size_t)bc * Nn;
    for (int i = t; i < 1024; i += 256) {
        int r = i >> 5, cl = i & 31;
        float acc = bias;
        #pragma unroll
        for (int dy = 0; dy < 7; dy++)
            #pragma unroll
            for (int dx = 0; dx < 7; dx++)
                acc += wsum[dy*7+dx] * tile[r+dy][cl+dx];
        op[i] = acc;
    }
}

// ---------------- kernel 2: layernorm over C per (b,n) -----------------------
__global__ void ln_kernel(const float* __restrict__ lnw, const float* __restrict__ lnb)
{
    int b    = blockIdx.x >> 5;
    int n0   = (blockIdx.x & 31) * 32;
    int lane = threadIdx.x & 31;
    int g    = threadIdx.x >> 5;
    int n    = n0 + lane;

    const float* base = g_yf + (size_t)b*Cc*Nn + n;
    float s = 0.f, s2 = 0.f;
    for (int c = g; c < Cc; c += 8) {
        float v = base[(size_t)c*Nn];
        s += v; s2 += v*v;
    }
    __shared__ float sh[2][8][32];
    sh[0][g][lane] = s; sh[1][g][lane] = s2;
    __syncthreads();
    if (g == 0) {
        float a = 0.f, a2 = 0.f;
        #pragma unroll
        for (int i = 0; i < 8; i++) { a += sh[0][i][lane]; a2 += sh[1][i][lane]; }
        float mu  = a * (1.f/512.f);
        float var = a2 * (1.f/512.f) - mu*mu;
        sh[0][0][lane] = mu;
        sh[1][0][lane] = rsqrtf(var + 1e-5f);
    }
    __syncthreads();
    float mu = sh[0][0][lane], rs = sh[1][0][lane];
    float* ob = g_yn + (size_t)b*Cc*Nn + n;
    for (int c = g; c < Cc; c += 8) {
        float v = base[(size_t)c*Nn];
        ob[(size_t)c*Nn] = (v - mu) * rs * lnw[c] + lnb[c];
    }
}

// ------- kernels 3/4: bf16 mma projection GEMM --------------------------------
// D[b,n,co] = sum_ci A[b,n,ci] * W[co,ci];  A,W,D bf16 (fp32 accum).
// CTA: 128n x 128co, K=512 in 8 chunks of 64. 8 warps (2n x 4co).
// Output co<512 -> D0[. , co], co>=512 -> D1[. , co-512].
#define GM_SMEM (2*128*PADB)
__global__ void __launch_bounds__(256, 2)
gemm_mma_kernel(const __nv_bfloat16* __restrict__ A, const __nv_bfloat16* __restrict__ W,
                __nv_bfloat16* __restrict__ D0, __nv_bfloat16* __restrict__ D1)
{
    extern __shared__ __align__(16) char sm[];
    const uint32_t AT = 0, WT = 128*PADB;
    uint32_t sb = smem_u32(sm);

    int t = threadIdx.x, warp = t >> 5, lane = t & 31;
    int co0 = blockIdx.x * 128, n0 = blockIdx.y * 128, b = blockIdx.z;
    int wn = warp >> 2, wm = warp & 3;

    const char* asrc = (const char*)(A + ((size_t)(b*Nn + n0))*Cc);
    const char* wsrc = (const char*)(W + (size_t)co0*Cc);

    float acc[4][4][4] = {};
    int lr16 = lane & 15, lh = lane >> 4;
    int l8 = lane & 7,  lq = (lane & 15) >> 3;

    for (int kc = 0; kc < Cc; kc += 64) {
        for (int i = t; i < 1024; i += 256) {        // 128 rows x 8 x 16B, per tile
            int row = i >> 3, cb = (i & 7) * 16;
            *(uint4*)(sm + AT + row*PADB + cb) =
                *(const uint4*)(asrc + (size_t)row*(Cc*2) + kc*2 + cb);
            *(uint4*)(sm + WT + row*PADB + cb) =
                *(const uint4*)(wsrc + (size_t)row*(Cc*2) + kc*2 + cb);
        }
        __syncthreads();
        uint32_t aAddr = sb + AT + (wn*64 + lr16)*PADB + lh*16;
        uint32_t bAddr = sb + WT + (wm*32 + l8)*PADB + lq*16;
        #pragma unroll
        for (int k0 = 0; k0 < 64; k0 += 16) {
            uint32_t a[4][4], bb[4][2];
            #pragma unroll
            for (int mi = 0; mi < 4; mi++)
                ldsm_x4(a[mi][0], a[mi][1], a[mi][2], a[mi][3],
                        aAddr + mi*16*PADB + k0*2);
            #pragma unroll
            for (int ni = 0; ni < 4; ni++)
                ldsm_x2(bb[ni][0], bb[ni][1], bAddr + ni*8*PADB + k0*2);
            #pragma unroll
            for (int mi = 0; mi < 4; mi++)
                #pragma unroll
                for (int ni = 0; ni < 4; ni++)
                    mma_bf16(acc[mi][ni], a[mi], bb[ni]);
        }
        __syncthreads();
    }

    __nv_bfloat16* D = (co0 < Cc) ? D0 : D1;
    int cadj = (co0 < Cc) ? 0 : Cc;
    int rbase = n0 + wn*64 + (lane >> 2);
    int cbase = co0 - cadj + wm*32 + (lane & 3)*2;
    #pragma unroll
    for (int mi = 0; mi < 4; mi++)
        #pragma unroll
        for (int ni = 0; ni < 4; ni++) {
            float* c = acc[mi][ni];
            size_t r0i = ((size_t)(b*Nn) + rbase + mi*16)*Cc + cbase + ni*8;
            __nv_bfloat162 p0, p1;
            p0.x = __float2bfloat16(c[0]); p0.y = __float2bfloat16(c[1]);
            p1.x = __float2bfloat16(c[2]); p1.y = __float2bfloat16(c[3]);
            *(__nv_bfloat162*)&D[r0i]        = p0;
            *(__nv_bfloat162*)&D[r0i + 8*Cc] = p1;
        }
}

// ---------- kernel 4c: v (bf16) -> transposed bf16 [z][d][m] ------------------
__global__ void split_vt_kernel()
{
    __shared__ __nv_bfloat16 tile[32][33];
    int d0 = blockIdx.x * 32, m0 = blockIdx.y * 32, z = blockIdx.z;
    int b = z >> 3, h = z & 7;
    int tx = threadIdx.x, ty = threadIdx.y;
    #pragma unroll
    for (int i = ty; i < 32; i += 8)
        tile[i][tx] = g_vbf[((size_t)(b*Nn + m0 + i))*Cc + h*64 + d0 + tx];
    __syncthreads();
    #pragma unroll
    for (int i = ty; i < 32; i += 8)
        g_vthi[((size_t)z*64 + d0 + i)*1024 + m0 + tx] = tile[tx][i];
}

// ---------------- kernel 5: QK^T via mma.sync bf16 (single pass) --------------
#define QK_SMEM (2*128*PADB)
__global__ void __launch_bounds__(256, 2) qk_mma_kernel()
{
    extern __shared__ __align__(16) char sm[];
    const uint32_t QT = 0, KT = 128*PADB;
    uint32_t sb = smem_u32(sm);

    int t = threadIdx.x, warp = t >> 5, lane = t & 31;
    int m0 = blockIdx.x * 128, n0 = blockIdx.y * 128, z = blockIdx.z;
    int b = z >> 3, h = z & 7;
    int wn = warp >> 2, wm = warp & 3;

    {
        const char* srcs[2] = {
            (const char*)(g_qbf + ((size_t)(b*Nn + n0)*Cc + h*64)),
            (const char*)(g_kbf + ((size_t)(b*Nn + m0)*Cc + h*64))};
        const uint32_t offs[2] = {QT, KT};
        #pragma unroll
        for (int tl = 0; tl < 2; tl++) {
            char* dst = sm + offs[tl];
            for (int i = t; i < 1024; i += 256) {
                int row = i >> 3, cb = (i & 7) * 16;
                *(uint4*)(dst + row*PADB + cb) =
                    *(const uint4*)(srcs[tl] + (size_t)row*(Cc*2) + cb);
            }
        }
    }
    __syncthreads();

    float acc[4][4][4] = {};
    int lr16 = lane & 15, lh = lane >> 4;
    int l8 = lane & 7,  lq = (lane & 15) >> 3;

    uint32_t aAddr = sb + QT + (wn*64 + lr16)*PADB + lh*16;
    uint32_t bAddr = sb + KT + (wm*32 + l8)*PADB + lq*16;
    #pragma unroll
    for (int k0 = 0; k0 < 64; k0 += 16) {
        uint32_t a[4][4], bb[4][2];
        #pragma unroll
        for (int mi = 0; mi < 4; mi++)
            ldsm_x4(a[mi][0], a[mi][1], a[mi][2], a[mi][3],
                    aAddr + mi*16*PADB + k0*2);
        #pragma unroll
        for (int ni = 0; ni < 4; ni++)
            ldsm_x2(bb[ni][0], bb[ni][1], bAddr + ni*8*PADB + k0*2);
        #pragma unroll
        for (int mi = 0; mi < 4; mi++)
            #pragma unroll
            for (int ni = 0; ni < 4; ni++)
                mma_bf16(acc[mi][ni], a[mi], bb[ni]);
    }

    int rbase = n0 + wn*64 + (lane >> 2);
    int cbase = m0 + wm*32 + (lane & 3)*2;
    #pragma unroll
    for (int mi = 0; mi < 4; mi++)
        #pragma unroll
        for (int ni = 0; ni < 4; ni++) {
            float* c = acc[mi][ni];
            size_t r0i = ((size_t)z*Nn + rbase + mi*16)*Nn + cbase + ni*8;
            *(float2*)&g_attn[r0i]          = make_float2(0.125f*c[0], 0.125f*c[1]);
            *(float2*)&g_attn[r0i + 8*Nn]   = make_float2(0.125f*c[2], 0.125f*c[3]);
        }
}

// ---------------- kernel 6: exact top-k + fused dual softmax -----------------
__device__ __forceinline__ float key2f(unsigned k) {
    unsigned b = (k & 0x80000000u) ? (k ^ 0x80000000u) : ~k;
    return __uint_as_float(b);
}

__device__ __forceinline__ unsigned kth_key(const unsigned* key, int k)
{
    unsigned prefix = 0;
    int kk = k;
    for (int bit = 31; bit >= 0; --bit) {
        unsigned bm = 1u << bit;
        unsigned hi = (bit == 31) ? 0u : (0xFFFFFFFFu << (bit+1));
        int c = 0;
        #pragma unroll
        for (int i = 0; i < 32; i++) {
            unsigned v = key[i];
            c += (((v & hi) == prefix) && (v & bm)) ? 1 : 0;
        }
        c = __reduce_add_sync(0xffffffffu, c);
        if (c == kk) {
            unsigned mn = 0xFFFFFFFFu;
            #pragma unroll
            for (int i = 0; i < 32; i++) {
                unsigned v = key[i];
                if (((v & hi) == prefix) && (v & bm)) mn = min(mn, v);
            }
            return __reduce_min_sync(0xffffffffu, mn);
        } else if (c > kk) {
            prefix |= bm;
        } else {
            kk -= c;
        }
    }
    return prefix;
}

__global__ void select_kernel(const float* __restrict__ kr1, const float* __restrict__ kr2)
{
    int row  = blockIdx.x * 8 + (threadIdx.x >> 5);   // z*1024 + n
    int lane = threadIdx.x & 31;

    float r1 = kr1[0], r2 = kr2[0];
    int k1 = (int)(1024.f * (1.f/(1.f+expf(-r1)))); k1 = min(max(k1,1),1024);
    int k2 = (int)(1024.f * (1.f/(1.f+expf(-r2)))); k2 = min(max(k2,1),1024);

    const float* rp = g_attn + (size_t)row * Nn;
    unsigned key[32];
    #pragma unroll
    for (int i = 0; i < 32; i++) {
        unsigned b = __float_as_uint(rp[i*32 + lane]);
        key[i] = (b & 0x80000000u) ? ~b : (b | 0x80000000u);
    }
    unsigned mx = 0;
    #pragma unroll
    for (int i = 0; i < 32; i++) mx = max(mx, key[i]);
    mx = __reduce_max_sync(0xffffffffu, mx);
    float M = key2f(mx);

    unsigned T1 = kth_key(key, k1);
    unsigned T2 = kth_key(key, k2);

    float s1 = 0.f, s2 = 0.f;
    #pragma unroll
    for (int i = 0; i < 32; i++) {
        float ev = __expf(key2f(key[i]) - M);
        if (key[i] >= T1) s1 += ev;
        if (key[i] >= T2) s2 += ev;
    }
    #pragma unroll
    for (int o = 16; o; o >>= 1) {
        s1 += __shfl_xor_sync(0xffffffffu, s1, o);
        s2 += __shfl_xor_sync(0xffffffffu, s2, o);
    }
    float c1 = 0.6f / s1, c2 = 0.4f / s2;
    __nv_bfloat16* ch = g_chi + (size_t)row * Nn;
    #pragma unroll
    for (int i = 0; i < 32; i++) {
        float w = (key[i] >= T1 ? c1 : 0.f) + (key[i] >= T2 ? c2 : 0.f);
        float cv = __expf(key2f(key[i]) - M) * w;
        ch[i*32 + lane] = __float2bfloat16(cv);
    }
}

// ---------------- kernel 7: AV via mma.sync bf16 (single pass) ----------------
#define AV_SMEM (128*PADB + 64*PADB)
__global__ void __launch_bounds__(256, 2) av_mma_kernel()
{
    extern __shared__ __align__(16) char sm[];
    const uint32_t CT = 0, VT = 128*PADB;
    uint32_t sb = smem_u32(sm);

    int t = threadIdx.x, warp = t >> 5, lane = t & 31;
    int n0 = blockIdx.x * 128, z = blockIdx.y;
    int b = z >> 3, h = z & 7;
    int wn = warp >> 1, wd = warp & 1;

    const char* ch = (const char*)(g_chi  + ((size_t)z*Nn + n0)*Nn);
    const char* vh = (const char*)(g_vthi + (size_t)z*64*1024);

    float acc[2][4][4] = {};
    int lr16 = lane & 15, lh = lane >> 4;
    int l8 = lane & 7,  lq = (lane & 15) >> 3;

    for (int m0 = 0; m0 < Nn; m0 += 64) {
        for (int i = t; i < 1024; i += 256) {
            int row = i >> 3, cb = (i & 7) * 16;
            size_t src = (size_t)row*2048 + m0*2 + cb;
            *(uint4*)(sm + CT + row*PADB + cb) = *(const uint4*)(ch + src);
        }
        for (int i = t; i < 512; i += 256) {
            int row = i >> 3, cb = (i & 7) * 16;
            size_t src = (size_t)row*2048 + m0*2 + cb;
            *(uint4*)(sm + VT + row*PADB + cb) = *(const uint4*)(vh + src);
        }
        __syncthreads();

        uint32_t aAddr = sb + CT + (wn*32 + lr16)*PADB + lh*16;
        uint32_t bAddr = sb + VT + (wd*32 + l8)*PADB + lq*16;
        #pragma unroll
        for (int k0 = 0; k0 < 64; k0 += 16) {
            uint32_t a[2][4], bb[4][2];
            #pragma unroll
            for (int mi = 0; mi < 2; mi++)
                ldsm_x4(a[mi][0], a[mi][1], a[mi][2], a[mi][3],
                        aAddr + mi*16*PADB + k0*2);
            #pragma unroll
            for (int ni = 0; ni < 4; ni++)
                ldsm_x2(bb[ni][0], bb[ni][1], bAddr + ni*8*PADB + k0*2);
            #pragma unroll
            for (int mi = 0; mi < 2; mi++)
                #pragma unroll
                for (int ni = 0; ni < 4; ni++)
                    mma_bf16(acc[mi][ni], a[mi], bb[ni]);
        }
        __syncthreads();
    }

    int rbase = n0 + wn*32 + (lane >> 2);
    int cbase = h*64 + wd*32 + (lane & 3)*2;
    #pragma unroll
    for (int mi = 0; mi < 2; mi++)
        #pragma unroll
        for (int ni = 0; ni < 4; ni++) {
            float* c = acc[mi][ni];
            size_t o0 = ((size_t)(b*Nn) + rbase + mi*16)*Cc + cbase + ni*8;
            *(float2*)&g_o[o0]        = make_float2(c[0], c[1]);
            *(float2*)&g_o[o0 + 8*Cc] = make_float2(c[2], c[3]);
        }
}

// ------- kernel 8: out[b,c,n] = proj_w[c,:].o[b,n,:] + b[c] + x[b,c,n] --------
__global__ void __launch_bounds__(256, 2)
proj_kernel(const float* __restrict__ Wt, const float* __restrict__ bias,
            const float* __restrict__ x, float* __restrict__ OUT)
{
    __shared__ float As[16][132];
    __shared__ float Bs[16][128];
    int c0 = blockIdx.x * 128, n0 = blockIdx.y * 128, b = blockIdx.z;
    int t = threadIdx.x, tx = t & 15, ty = t >> 4;

    int lr = t >> 1;
    int lk = (t & 1) * 8;
    int wr = t >> 4;
    int wc = (t & 15) * 8;

    float acc[8][8] = {};
    for (int k0 = 0; k0 < Cc; k0 += 16) {
        const float* ar = &g_o[((size_t)b*Nn + n0 + lr)*Cc + k0 + lk];
        float4 a0 = *(const float4*)ar; float4 a1 = *(const float4*)(ar + 4);
        As[lk+0][lr]=a0.x; As[lk+1][lr]=a0.y; As[lk+2][lr]=a0.z; As[lk+3][lr]=a0.w;
        As[lk+4][lr]=a1.x; As[lk+5][lr]=a1.y; As[lk+6][lr]=a1.z; As[lk+7][lr]=a1.w;
        const float* wrp = &Wt[(size_t)(k0 + wr)*Cc + c0 + wc];
        *(float4*)&Bs[wr][wc]   = *(const float4*)wrp;
        *(float4*)&Bs[wr][wc+4] = *(const float4*)(wrp + 4);
        __syncthreads();
        #pragma unroll
        for (int kk = 0; kk < 16; kk++) {
            float a[8], w[8];
            *(float4*)&a[0] = *(const float4*)&As[kk][ty*4];
            *(float4*)&a[4] = *(const float4*)&As[kk][64 + ty*4];
            *(float4*)&w[0] = *(const float4*)&Bs[kk][tx*4];
            *(float4*)&w[4] = *(const float4*)&Bs[kk][64 + tx*4];
            #pragma unroll
            for (int i = 0; i < 8; i++)
                #pragma unroll
                for (int j = 0; j < 8; j++) acc[i][j] += a[i]*w[j];
        }
        __syncthreads();
    }
    #pragma unroll
    for (int j = 0; j < 8; j++) {
        int c = c0 + (j < 4 ? tx*4 + j : 64 + tx*4 + (j-4));
        float bb = bias[c];
        size_t base = ((size_t)b*Cc + c)*Nn;
        int na = n0 + ty*4;
        float4 r0 = *(const float4*)&x[base + na];
        *(float4*)&OUT[base + na] = make_float4(acc[0][j]+bb+r0.x, acc[1][j]+bb+r0.y,
                                                acc[2][j]+bb+r0.z, acc[3][j]+bb+r0.w);
        int nb = n0 + 64 + ty*4;
        float4 r1 = *(const float4*)&x[base + nb];
        *(float4*)&OUT[base + nb] = make_float4(acc[4][j]+bb+r1.x, acc[5][j]+bb+r1.y,
                                                acc[6][j]+bb+r1.z, acc[7][j]+bb+r1.w);
    }
}

// -----------------------------------------------------------------------------
extern "C" void kernel_launch(void* const* d_in, const int* in_sizes, int n_in,
                              void* d_out, int out_size)
{
    const float* x       = (const float*)d_in[0];
    const float* y       = (const float*)d_in[1];
    const float* q_w     = (const float*)d_in[2];
    const float* kv_w    = (const float*)d_in[3];
    const float* proj_w  = (const float*)d_in[4];
    const float* proj_b  = (const float*)d_in[5];
    const float* conv1_w = (const float*)d_in[6];
    const float* conv1_b = (const float*)d_in[7];
    const float* conv2_w = (const float*)d_in[8];
    const float* conv2_b = (const float*)d_in[9];
    const float* conv3_w = (const float*)d_in[10];
    const float* conv3_b = (const float*)d_in[11];
    const float* ln_w    = (const float*)d_in[12];
    const float* ln_b    = (const float*)d_in[13];
    const float* kr1     = (const float*)d_in[14];
    const float* kr2     = (const float*)d_in[15];
    float* out = (float*)d_out;

    float *yn_p, *pwT;
    __nv_bfloat16 *xbf, *ynbf, *qwb, *kvwb, *qbf, *kbf, *vbf;
    cudaGetSymbolAddress((void**)&yn_p, g_yn);
    cudaGetSymbolAddress((void**)&pwT,  g_pwT);
    cudaGetSymbolAddress((void**)&xbf,  g_xbf);
    cudaGetSymbolAddress((void**)&ynbf, g_ynbf);
    cudaGetSymbolAddress((void**)&qwb,  g_qwb);
    cudaGetSymbolAddress((void**)&kvwb, g_kvwb);
    cudaGetSymbolAddress((void**)&qbf,  g_qbf);
    cudaGetSymbolAddress((void**)&kbf,  g_kbf);
    cudaGetSymbolAddress((void**)&vbf,  g_vbf);

    cudaFuncSetAttribute(gemm_mma_kernel, cudaFuncAttributeMaxDynamicSharedMemorySize, GM_SMEM);
    cudaFuncSetAttribute(qk_mma_kernel,   cudaFuncAttributeMaxDynamicSharedMemorySize, QK_SMEM);
    cudaFuncSetAttribute(av_mma_kernel,   cudaFuncAttributeMaxDynamicSharedMemorySize, AV_SMEM);

    dim3 tb(32, 8);
    transpose_kernel<<<dim3(16, 16), tb>>>(proj_w, pwT, Cc, Cc);
    wcvt_kernel<<<Cc*Cc/4/256, 256>>>(q_w,  qwb);
    wcvt_kernel<<<2*Cc*Cc/4/256, 256>>>(kv_w, kvwb);

    conv_kernel<<<Bz*Cc, 256>>>(y, conv1_w, conv1_b, conv2_w, conv2_b, conv3_w, conv3_b);
    ln_kernel<<<Bz*32, 256>>>(ln_w, ln_b);

    tcvt_kernel<<<dim3(32, 16, Bz), tb>>>(x,    xbf);
    tcvt_kernel<<<dim3(32, 16, Bz), tb>>>(yn_p, ynbf);

    gemm_mma_kernel<<<dim3(4, 8, Bz), 256, GM_SMEM>>>(xbf,  qwb,  qbf, qbf);
    gemm_mma_kernel<<<dim3(8, 8, Bz), 256, GM_SMEM>>>(ynbf, kvwb, kbf, vbf);

    split_vt_kernel<<<dim3(2, 32, 64), tb>>>();

    qk_mma_kernel<<<dim3(Nn/128, Nn/128, Bz*8), 256, QK_SMEM>>>();
    select_kernel<<<Bz*8*Nn/8, 256>>>(kr1, kr2);
    av_mma_kernel<<<dim3(Nn/128, Bz*8), 256, AV_SMEM>>>();
    proj_kernel<<<dim3(Cc/128, Nn/128, Bz), 256>>>(pwT, proj_b, x, out);
}

// round 8
// speedup vs baseline: 1.9372x; 1.2674x over previous
#include <cuda_runtime.h>
#include <cuda_bf16.h>
#include <cstdint>

#define Bz 8
#define Cc 512
#define Nn 1024

// ---------------- device scratch (no allocations allowed) --------------------
__device__ float g_yf[Bz*Cc*Nn];               // conv output [B,C,N]
__device__ float g_yn[Bz*Cc*Nn];               // layernorm output [B,C,N]
__device__ float g_attn[(size_t)64*1024*1024]; // attn [64 z][1024 n][1024 m] fp32
// bf16 operand buffers
__device__ __nv_bfloat16 g_xbf [Bz*Nn*Cc];     // x^T  [b,n,512]
__device__ __nv_bfloat16 g_ynbf[Bz*Nn*Cc];     // yn^T [b,n,512]
__device__ __nv_bfloat16 g_qwb [Cc*Cc];        // 0.125*q_w  [co,512]
__device__ __nv_bfloat16 g_kvwb[2*Cc*Cc];      // kv_w [co,512]
__device__ __nv_bfloat16 g_pwb [Cc*Cc];        // proj_w [co,512]
__device__ __nv_bfloat16 g_qbf [Bz*Nn*Cc];     // q  [b,n,512]
__device__ __nv_bfloat16 g_kbf [Bz*Nn*Cc];     // k  [b,n,512]
__device__ __nv_bfloat16 g_vbf [Bz*Nn*Cc];     // v  [b,n,512]
__device__ __nv_bfloat16 g_obf [Bz*Nn*Cc];     // attn out [b,n,512]
__device__ __nv_bfloat16 g_vthi[(size_t)64*64*1024];   // v^T [z,d,m]
__device__ __nv_bfloat16 g_chi [(size_t)64*1024*1024]; // coeff [z,n,m]

// =================== warp-MMA helpers (plain sm_103-safe PTX) ================
__device__ __forceinline__ uint32_t smem_u32(const void* p) {
    uint32_t a;
    asm("{ .reg .u64 t; cvta.to.shared.u64 t, %1; cvt.u32.u64 %0, t; }"
        : "=r"(a) : "l"(p));
    return a;
}
__device__ __forceinline__ void ldsm_x4(uint32_t& r0, uint32_t& r1, uint32_t& r2,
                                        uint32_t& r3, uint32_t addr) {
    asm volatile("ldmatrix.sync.aligned.m8n8.x4.shared.b16 {%0,%1,%2,%3}, [%4];"
                 : "=r"(r0), "=r"(r1), "=r"(r2), "=r"(r3) : "r"(addr));
}
__device__ __forceinline__ void ldsm_x2(uint32_t& r0, uint32_t& r1, uint32_t addr) {
    asm volatile("ldmatrix.sync.aligned.m8n8.x2.shared.b16 {%0,%1}, [%2];"
                 : "=r"(r0), "=r"(r1) : "r"(addr));
}
__device__ __forceinline__ void mma_bf16(float* c, const uint32_t* a, const uint32_t* b) {
    asm volatile("mma.sync.aligned.m16n8k16.row.col.f32.bf16.bf16.f32 "
                 "{%0,%1,%2,%3}, {%4,%5,%6,%7}, {%8,%9}, {%0,%1,%2,%3};"
                 : "+f"(c[0]), "+f"(c[1]), "+f"(c[2]), "+f"(c[3])
                 : "r"(a[0]), "r"(a[1]), "r"(a[2]), "r"(a[3]), "r"(b[0]), "r"(b[1]));
}
#define CP_ASYNC16(dst, src) \
    asm volatile("cp.async.cg.shared.global [%0], [%1], 16;" :: "r"(dst), "l"(src))
#define CP_COMMIT() asm volatile("cp.async.commit_group;" ::: "memory")
#define CP_WAIT(n)  asm volatile("cp.async.wait_group %0;" :: "n"(n) : "memory")
#define PADB 144   // padded row stride (72 bf16): conflict-free ldmatrix, 16B-mult

// ---------------- kernel 0a: fp32 -> bf16 scaled convert ---------------------
__global__ void wcvt_kernel(const float* __restrict__ S, __nv_bfloat16* __restrict__ D,
                            float scale)
{
    int i4 = blockIdx.x * 256 + threadIdx.x;
    float4 v = *(const float4*)&S[(size_t)i4 * 4];
    __nv_bfloat16 o[4] = {__float2bfloat16(v.x*scale), __float2bfloat16(v.y*scale),
                          __float2bfloat16(v.z*scale), __float2bfloat16(v.w*scale)};
    *(uint2*)&D[(size_t)i4 * 4] = *(uint2*)o;
}

// ------- kernel 0b: [B,C,N] fp32 -> [B,N,C] bf16 transpose-convert -----------
__global__ void tcvt_kernel(const float* __restrict__ S, __nv_bfloat16* __restrict__ D)
{
    __shared__ float tile[32][33];
    int n0 = blockIdx.x * 32, c0 = blockIdx.y * 32, b = blockIdx.z;
    int tx = threadIdx.x, ty = threadIdx.y;
    #pragma unroll
    for (int i = ty; i < 32; i += 8)
        tile[i][tx] = S[((size_t)b*Cc + c0 + i)*Nn + n0 + tx];
    __syncthreads();
    #pragma unroll
    for (int i = ty; i < 32; i += 8)
        D[((size_t)b*Nn + n0 + i)*Cc + c0 + tx] = __float2bfloat16(tile[tx][i]);
}

// ---------------- kernel 1: fused multi-scale depthwise conv -----------------
__global__ void conv_kernel(const float* __restrict__ y,
                            const float* __restrict__ w3, const float* __restrict__ b3,
                            const float* __restrict__ w5, const float* __restrict__ b5,
                            const float* __restrict__ w7, const float* __restrict__ b7)
{
    int bc = blockIdx.x;
    int c  = bc & (Cc-1);
    int t  = threadIdx.x;

    __shared__ float tile[38][38];
    __shared__ float wsum[49];
    __shared__ float bias;

    if (t < 49) {
        int dy = t / 7, dx = t % 7;
        float w = w7[c*49 + t];
        if (dy >= 1 && dy <= 5 && dx >= 1 && dx <= 5) w += w5[c*25 + (dy-1)*5 + (dx-1)];
        if (dy >= 2 && dy <= 4 && dx >= 2 && dx <= 4) w += w3[c*9  + (dy-2)*3 + (dx-2)];
        wsum[t] = w;
    }
    if (t == 64) bias = b3[c] + b5[c] + b7[c];

    const float* yp = y + (size_t)bc * Nn;
    for (int i = t; i < 38*38; i += 256) {
        int r  = i / 38 - 3;
        int cl = i % 38 - 3;
        float v = 0.f;
        if (r >= 0 && r < 32 && cl >= 0 && cl < 32) v = yp[r*32 + cl];
        tile[i/38][i%38] = v;
    }
    __syncthreads();

    float* op = g_yf + (size_t)bc * Nn;
    for (int i = t; i < 1024; i += 256) {
        int r = i >> 5, cl = i & 31;
        float acc = bias;
        #pragma unroll
        for (int dy = 0; dy < 7; dy++)
            #pragma unroll
            for (int dx = 0; dx < 7; dx++)
                acc += wsum[dy*7+dx] * tile[r+dy][cl+dx];
        op[i] = acc;
    }
}

// ---------------- kernel 2: layernorm over C per (b,n) -----------------------
__global__ void ln_kernel(const float* __restrict__ lnw, const float* __restrict__ lnb)
{
    int b    = blockIdx.x >> 5;
    int n0   = (blockIdx.x & 31) * 32;
    int lane = threadIdx.x & 31;
    int g    = threadIdx.x >> 5;
    int n    = n0 + lane;

    const float* base = g_yf + (size_t)b*Cc*Nn + n;
    float s = 0.f, s2 = 0.f;
    for (int c = g; c < Cc; c += 8) {
        float v = base[(size_t)c*Nn];
        s += v; s2 += v*v;
    }
    __shared__ float sh[2][8][32];
    sh[0][g][lane] = s; sh[1][g][lane] = s2;
    __syncthreads();
    if (g == 0) {
        float a = 0.f, a2 = 0.f;
        #pragma unroll
        for (int i = 0; i < 8; i++) { a += sh[0][i][lane]; a2 += sh[1][i][lane]; }
        float mu  = a * (1.f/512.f);
        float var = a2 * (1.f/512.f) - mu*mu;
        sh[0][0][lane] = mu;
        sh[1][0][lane] = rsqrtf(var + 1e-5f);
    }
    __syncthreads();
    float mu = sh[0][0][lane], rs = sh[1][0][lane];
    float* ob = g_yn + (size_t)b*Cc*Nn + n;
    for (int c = g; c < Cc; c += 8) {
        float v = base[(size_t)c*Nn];
        ob[(size_t)c*Nn] = (v - mu) * rs * lnw[c] + lnb[c];
    }
}

// ------- kernels 3/4: bf16 mma projection GEMM, double-buffered cp.async -----
// D[b,n,co] = sum_ci A[b,n,ci] * W[co,ci]; co<512 -> D0, co>=512 -> D1[co-512].
#define GM_SMEM (4*128*PADB)
__global__ void __launch_bounds__(256, 2)
gemm_mma_kernel(const __nv_bfloat16* __restrict__ A, const __nv_bfloat16* __restrict__ W,
                __nv_bfloat16* __restrict__ D0, __nv_bfloat16* __restrict__ D1)
{
    extern __shared__ __align__(16) char sm[];
    uint32_t sb = smem_u32(sm);

    int t = threadIdx.x, warp = t >> 5, lane = t & 31;
    int co0 = blockIdx.x * 128, n0 = blockIdx.y * 128, b = blockIdx.z;
    int wn = warp >> 2, wm = warp & 3;

    const char* asrc = (const char*)(A + ((size_t)(b*Nn + n0))*Cc);
    const char* wsrc = (const char*)(W + (size_t)co0*Cc);

    // issue chunk kc (bytes offset kc*2) into buffer bi
    auto issue = [&](int kc, int bi) {
        uint32_t base = sb + bi*(2*128*PADB);
        for (int i = t; i < 1024; i += 256) {
            int row = i >> 3, cb = (i & 7) * 16;
            CP_ASYNC16(base + row*PADB + cb, asrc + (size_t)row*1024 + kc*2 + cb);
            CP_ASYNC16(base + 128*PADB + row*PADB + cb, wsrc + (size_t)row*1024 + kc*2 + cb);
        }
        CP_COMMIT();
    };
    issue(0, 0);

    float acc[4][4][4] = {};
    int lr16 = lane & 15, lh = lane >> 4;
    int l8 = lane & 7,  lq = (lane & 15) >> 3;

    for (int c8 = 0; c8 < 8; c8++) {
        if (c8 < 7) { issue((c8+1)*64, (c8+1)&1); CP_WAIT(1); }
        else        { CP_WAIT(0); }
        __syncthreads();
        uint32_t base = sb + (c8&1)*(2*128*PADB);
        uint32_t aAddr = base + (wn*64 + lr16)*PADB + lh*16;
        uint32_t bAddr = base + 128*PADB + (wm*32 + l8)*PADB + lq*16;
        #pragma unroll
        for (int k0 = 0; k0 < 64; k0 += 16) {
            uint32_t a[4][4], bb[4][2];
            #pragma unroll
            for (int mi = 0; mi < 4; mi++)
                ldsm_x4(a[mi][0], a[mi][1], a[mi][2], a[mi][3],
                        aAddr + mi*16*PADB + k0*2);
            #pragma unroll
            for (int ni = 0; ni < 4; ni++)
                ldsm_x2(bb[ni][0], bb[ni][1], bAddr + ni*8*PADB + k0*2);
            #pragma unroll
            for (int mi = 0; mi < 4; mi++)
                #pragma unroll
                for (int ni = 0; ni < 4; ni++)
                    mma_bf16(acc[mi][ni], a[mi], bb[ni]);
        }
        __syncthreads();
    }

    __nv_bfloat16* D = (co0 < Cc) ? D0 : D1;
    int cadj = (co0 < Cc) ? 0 : Cc;
    int rbase = n0 + wn*64 + (lane >> 2);
    int cbase = co0 - cadj + wm*32 + (lane & 3)*2;
    #pragma unroll
    for (int mi = 0; mi < 4; mi++)
        #pragma unroll
        for (int ni = 0; ni < 4; ni++) {
            float* c = acc[mi][ni];
            size_t r0i = ((size_t)(b*Nn) + rbase + mi*16)*Cc + cbase + ni*8;
            __nv_bfloat162 p0, p1;
            p0.x = __float2bfloat16(c[0]); p0.y = __float2bfloat16(c[1]);
            p1.x = __float2bfloat16(c[2]); p1.y = __float2bfloat16(c[3]);
            *(__nv_bfloat162*)&D[r0i]        = p0;
            *(__nv_bfloat162*)&D[r0i + 8*Cc] = p1;
        }
}

// ---------- kernel 4c: v (bf16) -> transposed bf16 [z][d][m] ------------------
__global__ void split_vt_kernel()
{
    __shared__ __nv_bfloat16 tile[32][33];
    int d0 = blockIdx.x * 32, m0 = blockIdx.y * 32, z = blockIdx.z;
    int b = z >> 3, h = z & 7;
    int tx = threadIdx.x, ty = threadIdx.y;
    #pragma unroll
    for (int i = ty; i < 32; i += 8)
        tile[i][tx] = g_vbf[((size_t)(b*Nn + m0 + i))*Cc + h*64 + d0 + tx];
    __syncthreads();
    #pragma unroll
    for (int i = ty; i < 32; i += 8)
        g_vthi[((size_t)z*64 + d0 + i)*1024 + m0 + tx] = tile[tx][i];
}

// ---------------- kernel 5: QK^T via mma.sync bf16 (scale pre-folded) --------
#define QK_SMEM (2*128*PADB)
__global__ void __launch_bounds__(256, 2) qk_mma_kernel()
{
    extern __shared__ __align__(16) char sm[];
    const uint32_t QT = 0, KT = 128*PADB;
    uint32_t sb = smem_u32(sm);

    int t = threadIdx.x, warp = t >> 5, lane = t & 31;
    int m0 = blockIdx.x * 128, n0 = blockIdx.y * 128, z = blockIdx.z;
    int b = z >> 3, h = z & 7;
    int wn = warp >> 2, wm = warp & 3;

    {
        const char* srcs[2] = {
            (const char*)(g_qbf + ((size_t)(b*Nn + n0)*Cc + h*64)),
            (const char*)(g_kbf + ((size_t)(b*Nn + m0)*Cc + h*64))};
        const uint32_t offs[2] = {QT, KT};
        #pragma unroll
        for (int tl = 0; tl < 2; tl++) {
            uint32_t dst = sb + offs[tl];
            for (int i = t; i < 1024; i += 256) {
                int row = i >> 3, cb = (i & 7) * 16;
                CP_ASYNC16(dst + row*PADB + cb, srcs[tl] + (size_t)row*(Cc*2) + cb);
            }
        }
        CP_COMMIT();
        CP_WAIT(0);
    }
    __syncthreads();

    float acc[4][4][4] = {};
    int lr16 = lane & 15, lh = lane >> 4;
    int l8 = lane & 7,  lq = (lane & 15) >> 3;

    uint32_t aAddr = sb + QT + (wn*64 + lr16)*PADB + lh*16;
    uint32_t bAddr = sb + KT + (wm*32 + l8)*PADB + lq*16;
    #pragma unroll
    for (int k0 = 0; k0 < 64; k0 += 16) {
        uint32_t a[4][4], bb[4][2];
        #pragma unroll
        for (int mi = 0; mi < 4; mi++)
            ldsm_x4(a[mi][0], a[mi][1], a[mi][2], a[mi][3],
                    aAddr + mi*16*PADB + k0*2);
        #pragma unroll
        for (int ni = 0; ni < 4; ni++)
            ldsm_x2(bb[ni][0], bb[ni][1], bAddr + ni*8*PADB + k0*2);
        #pragma unroll
        for (int mi = 0; mi < 4; mi++)
            #pragma unroll
            for (int ni = 0; ni < 4; ni++)
                mma_bf16(acc[mi][ni], a[mi], bb[ni]);
    }

    int rbase = n0 + wn*64 + (lane >> 2);
    int cbase = m0 + wm*32 + (lane & 3)*2;
    #pragma unroll
    for (int mi = 0; mi < 4; mi++)
        #pragma unroll
        for (int ni = 0; ni < 4; ni++) {
            float* c = acc[mi][ni];
            size_t r0i = ((size_t)z*Nn + rbase + mi*16)*Nn + cbase + ni*8;
            *(float2*)&g_attn[r0i]        = make_float2(c[0], c[1]);
            *(float2*)&g_attn[r0i + 8*Nn] = make_float2(c[2], c[3]);
        }
}

// ---------------- kernel 6: exact top-k + fused dual softmax -----------------
__device__ __forceinline__ float key2f(unsigned k) {
    unsigned b = (k & 0x80000000u) ? (k ^ 0x80000000u) : ~k;
    return __uint_as_float(b);
}

__device__ __forceinline__ unsigned kth_key(const unsigned* key, int k)
{
    unsigned prefix = 0;
    int kk = k;
    for (int bit = 31; bit >= 0; --bit) {
        unsigned bm = 1u << bit;
        unsigned hi = (bit == 31) ? 0u : (0xFFFFFFFFu << (bit+1));
        int c = 0;
        #pragma unroll
        for (int i = 0; i < 32; i++) {
            unsigned v = key[i];
            c += (((v & hi) == prefix) && (v & bm)) ? 1 : 0;
        }
        c = __reduce_add_sync(0xffffffffu, c);
        if (c == kk) {
            unsigned mn = 0xFFFFFFFFu;
            #pragma unroll
            for (int i = 0; i < 32; i++) {
                unsigned v = key[i];
                if (((v & hi) == prefix) && (v & bm)) mn = min(mn, v);
            }
            return __reduce_min_sync(0xffffffffu, mn);
        } else if (c > kk) {
            prefix |= bm;
        } else {
            kk -= c;
        }
    }
    return prefix;
}

__global__ void select_kernel(const float* __restrict__ kr1, const float* __restrict__ kr2)
{
    int row  = blockIdx.x * 8 + (threadIdx.x >> 5);   // z*1024 + n
    int lane = threadIdx.x & 31;

    float r1 = kr1[0], r2 = kr2[0];
    int k1 = (int)(1024.f * (1.f/(1.f+expf(-r1)))); k1 = min(max(k1,1),1024);
    int k2 = (int)(1024.f * (1.f/(1.f+expf(-r2)))); k2 = min(max(k2,1),1024);

    const float* rp = g_attn + (size_t)row * Nn;
    unsigned key[32];
    #pragma unroll
    for (int i = 0; i < 32; i++) {
        unsigned b = __float_as_uint(rp[i*32 + lane]);
        key[i] = (b & 0x80000000u) ? ~b : (b | 0x80000000u);
    }
    unsigned mx = 0;
    #pragma unroll
    for (int i = 0; i < 32; i++) mx = max(mx, key[i]);
    mx = __reduce_max_sync(0xffffffffu, mx);
    float M = key2f(mx);

    unsigned T1 = kth_key(key, k1);
    unsigned T2 = kth_key(key, k2);

    float s1 = 0.f, s2 = 0.f;
    #pragma unroll
    for (int i = 0; i < 32; i++) {
        float ev = __expf(key2f(key[i]) - M);
        if (key[i] >= T1) s1 += ev;
        if (key[i] >= T2) s2 += ev;
    }
    #pragma unroll
    for (int o = 16; o; o >>= 1) {
        s1 += __shfl_xor_sync(0xffffffffu, s1, o);
        s2 += __shfl_xor_sync(0xffffffffu, s2, o);
    }
    float c1 = 0.6f / s1, c2 = 0.4f / s2;
    __nv_bfloat16* ch = g_chi + (size_t)row * Nn;
    #pragma unroll
    for (int i = 0; i < 32; i++) {
        float w = (key[i] >= T1 ? c1 : 0.f) + (key[i] >= T2 ? c2 : 0.f);
        float cv = __expf(key2f(key[i]) - M) * w;
        ch[i*32 + lane] = __float2bfloat16(cv);
    }
}

// ------- kernel 7: AV via mma.sync bf16, double-buffered, bf16 output --------
#define AV_SMEM (2*(192*PADB))
__global__ void __launch_bounds__(256, 2) av_mma_kernel()
{
    extern __shared__ __align__(16) char sm[];
    uint32_t sb = smem_u32(sm);

    int t = threadIdx.x, warp = t >> 5, lane = t & 31;
    int n0 = blockIdx.x * 128, z = blockIdx.y;
    int b = z >> 3, h = z & 7;
    int wn = warp >> 1, wd = warp & 1;

    const char* ch = (const char*)(g_chi  + ((size_t)z*Nn + n0)*Nn);
    const char* vh = (const char*)(g_vthi + (size_t)z*64*1024);

    auto issue = [&](int m0, int bi) {
        uint32_t base = sb + bi*(192*PADB);
        for (int i = t; i < 1024; i += 256) {
            int row = i >> 3, cb = (i & 7) * 16;
            CP_ASYNC16(base + row*PADB + cb, ch + (size_t)row*2048 + m0*2 + cb);
        }
        for (int i = t; i < 512; i += 256) {
            int row = i >> 3, cb = (i & 7) * 16;
            CP_ASYNC16(base + 128*PADB + row*PADB + cb, vh + (size_t)row*2048 + m0*2 + cb);
        }
        CP_COMMIT();
    };
    issue(0, 0);

    float acc[2][4][4] = {};
    int lr16 = lane & 15, lh = lane >> 4;
    int l8 = lane & 7,  lq = (lane & 15) >> 3;

    for (int c16 = 0; c16 < 16; c16++) {
        if (c16 < 15) { issue((c16+1)*64, (c16+1)&1); CP_WAIT(1); }
        else          { CP_WAIT(0); }
        __syncthreads();
        uint32_t base = sb + (c16&1)*(192*PADB);
        uint32_t aAddr = base + (wn*32 + lr16)*PADB + lh*16;
        uint32_t bAddr = base + 128*PADB + (wd*32 + l8)*PADB + lq*16;
        #pragma unroll
        for (int k0 = 0; k0 < 64; k0 += 16) {
            uint32_t a[2][4], bb[4][2];
            #pragma unroll
            for (int mi = 0; mi < 2; mi++)
                ldsm_x4(a[mi][0], a[mi][1], a[mi][2], a[mi][3],
                        aAddr + mi*16*PADB + k0*2);
            #pragma unroll
            for (int ni = 0; ni < 4; ni++)
                ldsm_x2(bb[ni][0], bb[ni][1], bAddr + ni*8*PADB + k0*2);
            #pragma unroll
            for (int mi = 0; mi < 2; mi++)
                #pragma unroll
                for (int ni = 0; ni < 4; ni++)
                    mma_bf16(acc[mi][ni], a[mi], bb[ni]);
        }
        __syncthreads();
    }

    int rbase = n0 + wn*32 + (lane >> 2);
    int cbase = h*64 + wd*32 + (lane & 3)*2;
    #pragma unroll
    for (int mi = 0; mi < 2; mi++)
        #pragma unroll
        for (int ni = 0; ni < 4; ni++) {
            float* c = acc[mi][ni];
            size_t o0 = ((size_t)(b*Nn) + rbase + mi*16)*Cc + cbase + ni*8;
            __nv_bfloat162 p0, p1;
            p0.x = __float2bfloat16(c[0]); p0.y = __float2bfloat16(c[1]);
            p1.x = __float2bfloat16(c[2]); p1.y = __float2bfloat16(c[3]);
            *(__nv_bfloat162*)&g_obf[o0]        = p0;
            *(__nv_bfloat162*)&g_obf[o0 + 8*Cc] = p1;
        }
}

// ------- kernel 8: proj via mma; out[b,c,n] = W.o + bias + x ------------------
// A = proj_w [c][k] (rows = c), B = o [n][k] -> acc[c][n]; coalesced-in-n output.
#define PJ_SMEM (4*128*PADB)
__global__ void __launch_bounds__(256, 2)
proj_mma_kernel(const float* __restrict__ bias, const float* __restrict__ x,
                float* __restrict__ OUT)
{
    extern __shared__ __align__(16) char sm[];
    uint32_t sb = smem_u32(sm);

    int t = threadIdx.x, warp = t >> 5, lane = t & 31;
    int c0 = blockIdx.x * 128, n0 = blockIdx.y * 128, b = blockIdx.z;
    int wc = warp >> 2, wnn = warp & 3;      // 2 c-warps x 4 n-warps

    const char* wsrc = (const char*)(g_pwb + (size_t)c0*Cc);
    const char* osrc = (const char*)(g_obf + ((size_t)(b*Nn + n0))*Cc);

    auto issue = [&](int kc, int bi) {
        uint32_t base = sb + bi*(2*128*PADB);
        for (int i = t; i < 1024; i += 256) {
            int row = i >> 3, cb = (i & 7) * 16;
            CP_ASYNC16(base + row*PADB + cb, wsrc + (size_t)row*1024 + kc*2 + cb);
            CP_ASYNC16(base + 128*PADB + row*PADB + cb, osrc + (size_t)row*1024 + kc*2 + cb);
        }
        CP_COMMIT();
    };
    issue(0, 0);

    float acc[4][4][4] = {};                  // [mi(c)][ni(n)][4]
    int lr16 = lane & 15, lh = lane >> 4;
    int l8 = lane & 7,  lq = (lane & 15) >> 3;

    for (int c8 = 0; c8 < 8; c8++) {
        if (c8 < 7) { issue((c8+1)*64, (c8+1)&1); CP_WAIT(1); }
        else        { CP_WAIT(0); }
        __syncthreads();
        uint32_t base = sb + (c8&1)*(2*128*PADB);
        uint32_t aAddr = base + (wc*64 + lr16)*PADB + lh*16;
        uint32_t bAddr = base + 128*PADB + (wnn*32 + l8)*PADB + lq*16;
        #pragma unroll
        for (int k0 = 0; k0 < 64; k0 += 16) {
            uint32_t a[4][4], bb[4][2];
            #pragma unroll
            for (int mi = 0; mi < 4; mi++)
                ldsm_x4(a[mi][0], a[mi][1], a[mi][2], a[mi][3],
                        aAddr + mi*16*PADB + k0*2);
            #pragma unroll
            for (int ni = 0; ni < 4; ni++)
                ldsm_x2(bb[ni][0], bb[ni][1], bAddr + ni*8*PADB + k0*2);
            #pragma unroll
            for (int mi = 0; mi < 4; mi++)
                #pragma unroll
                for (int ni = 0; ni < 4; ni++)
                    mma_bf16(acc[mi][ni], a[mi], bb[ni]);
        }
        __syncthreads();
    }

    int cb0 = c0 + wc*64 + (lane >> 2);
    int nb0 = n0 + wnn*32 + (lane & 3)*2;
    #pragma unroll
    for (int mi = 0; mi < 4; mi++) {
        int c = cb0 + mi*16;
        float bs0 = bias[c], bs8 = bias[c + 8];
        #pragma unroll
        for (int ni = 0; ni < 4; ni++) {
            float* a = acc[mi][ni];
            int n = nb0 + ni*8;
            size_t i0 = ((size_t)b*Cc + c)*Nn + n;
            float2 x0 = *(const float2*)&x[i0];
            *(float2*)&OUT[i0] = make_float2(a[0] + bs0 + x0.x, a[1] + bs0 + x0.y);
            size_t i8 = i0 + (size_t)8*Nn;
            float2 x8 = *(const float2*)&x[i8];
            *(float2*)&OUT[i8] = make_float2(a[2] + bs8 + x8.x, a[3] + bs8 + x8.y);
        }
    }
}

// -----------------------------------------------------------------------------
extern "C" void kernel_launch(void* const* d_in, const int* in_sizes, int n_in,
                              void* d_out, int out_size)
{
    const float* x       = (const float*)d_in[0];
    const float* y       = (const float*)d_in[1];
    const float* q_w     = (const float*)d_in[2];
    const float* kv_w    = (const float*)d_in[3];
    const float* proj_w  = (const float*)d_in[4];
    const float* proj_b  = (const float*)d_in[5];
    const float* conv1_w = (const float*)d_in[6];
    const float* conv1_b = (const float*)d_in[7];
    const float* conv2_w = (const float*)d_in[8];
    const float* conv2_b = (const float*)d_in[9];
    const float* conv3_w = (const float*)d_in[10];
    const float* conv3_b = (const float*)d_in[11];
    const float* ln_w    = (const float*)d_in[12];
    const float* ln_b    = (const float*)d_in[13];
    const float* kr1     = (const float*)d_in[14];
    const float* kr2     = (const float*)d_in[15];
    float* out = (float*)d_out;

    float* yn_p;
    __nv_bfloat16 *xbf, *ynbf, *qwb, *kvwb, *pwb, *qbf, *kbf, *vbf;
    cudaGetSymbolAddress((void**)&yn_p, g_yn);
    cudaGetSymbolAddress((void**)&xbf,  g_xbf);
    cudaGetSymbolAddress((void**)&ynbf, g_ynbf);
    cudaGetSymbolAddress((void**)&qwb,  g_qwb);
    cudaGetSymbolAddress((void**)&kvwb, g_kvwb);
    cudaGetSymbolAddress((void**)&pwb,  g_pwb);
    cudaGetSymbolAddress((void**)&qbf,  g_qbf);
    cudaGetSymbolAddress((void**)&kbf,  g_kbf);
    cudaGetSymbolAddress((void**)&vbf,  g_vbf);

    cudaFuncSetAttribute(gemm_mma_kernel, cudaFuncAttributeMaxDynamicSharedMemorySize, GM_SMEM);
    cudaFuncSetAttribute(qk_mma_kernel,   cudaFuncAttributeMaxDynamicSharedMemorySize, QK_SMEM);
    cudaFuncSetAttribute(av_mma_kernel,   cudaFuncAttributeMaxDynamicSharedMemorySize, AV_SMEM);
    cudaFuncSetAttribute(proj_mma_kernel, cudaFuncAttributeMaxDynamicSharedMemorySize, PJ_SMEM);

    dim3 tb(32, 8);
    wcvt_kernel<<<Cc*Cc/4/256, 256>>>(q_w,    qwb,  0.125f);
    wcvt_kernel<<<2*Cc*Cc/4/256, 256>>>(kv_w, kvwb, 1.f);
    wcvt_kernel<<<Cc*Cc/4/256, 256>>>(proj_w, pwb,  1.f);

    conv_kernel<<<Bz*Cc, 256>>>(y, conv1_w, conv1_b, conv2_w, conv2_b, conv3_w, conv3_b);
    ln_kernel<<<Bz*32, 256>>>(ln_w, ln_b);

    tcvt_kernel<<<dim3(32, 16, Bz), tb>>>(x,    xbf);
    tcvt_kernel<<<dim3(32, 16, Bz), tb>>>(yn_p, ynbf);

    gemm_mma_kernel<<<dim3(4, 8, Bz), 256, GM_SMEM>>>(xbf,  qwb,  qbf, qbf);
    gemm_mma_kernel<<<dim3(8, 8, Bz), 256, GM_SMEM>>>(ynbf, kvwb, kbf, vbf);

    split_vt_kernel<<<dim3(2, 32, 64), tb>>>();

    qk_mma_kernel<<<dim3(Nn/128, Nn/128, Bz*8), 256, QK_SMEM>>>();
    select_kernel<<<Bz*8*Nn/8, 256>>>(kr1, kr2);
    av_mma_kernel<<<dim3(Nn/128, Bz*8), 256, AV_SMEM>>>();
    proj_mma_kernel<<<dim3(Cc/128, Nn/128, Bz), 256, PJ_SMEM>>>(proj_b, x, out);
}

// round 9
// speedup vs baseline: 2.5493x; 1.3160x over previous
#include <cuda_runtime.h>
#include <cuda_bf16.h>
#include <cuda_fp16.h>
#include <cstdint>

#define Bz 8
#define Cc 512
#define Nn 1024

// ---------------- device scratch (no allocations allowed) --------------------
__device__ float g_yf[Bz*Cc*Nn];               // conv output [B,C,N]
__device__ float g_yn[Bz*Cc*Nn];               // layernorm output [B,C,N]
__device__ __half g_attnh[(size_t)64*1024*1024]; // attn [64 z][1024 n][1024 m] fp16
// bf16 operand buffers
__device__ __nv_bfloat16 g_xbf [Bz*Nn*Cc];     // x^T  [b,n,512]
__device__ __nv_bfloat16 g_ynbf[Bz*Nn*Cc];     // yn^T [b,n,512]
__device__ __nv_bfloat16 g_qwb [Cc*Cc];        // 0.125*q_w  [co,512]
__device__ __nv_bfloat16 g_kvwb[2*Cc*Cc];      // kv_w [co,512]
__device__ __nv_bfloat16 g_pwb [Cc*Cc];        // proj_w [co,512]
__device__ __nv_bfloat16 g_qbf [Bz*Nn*Cc];     // q  [b,n,512]
__device__ __nv_bfloat16 g_kbf [Bz*Nn*Cc];     // k  [b,n,512]
__device__ __nv_bfloat16 g_vbf [Bz*Nn*Cc];     // v  [b,n,512]
__device__ __nv_bfloat16 g_obf [Bz*Nn*Cc];     // attn out [b,n,512]
__device__ __nv_bfloat16 g_vthi[(size_t)64*64*1024];   // v^T [z,d,m]
__device__ __nv_bfloat16 g_chi [(size_t)64*1024*1024]; // coeff [z,n,m]

// =================== warp-MMA helpers (plain sm_103-safe PTX) ================
__device__ __forceinline__ uint32_t smem_u32(const void* p) {
    uint32_t a;
    asm("{ .reg .u64 t; cvta.to.shared.u64 t, %1; cvt.u32.u64 %0, t; }"
        : "=r"(a) : "l"(p));
    return a;
}
__device__ __forceinline__ void ldsm_x4(uint32_t& r0, uint32_t& r1, uint32_t& r2,
                                        uint32_t& r3, uint32_t addr) {
    asm volatile("ldmatrix.sync.aligned.m8n8.x4.shared.b16 {%0,%1,%2,%3}, [%4];"
                 : "=r"(r0), "=r"(r1), "=r"(r2), "=r"(r3) : "r"(addr));
}
__device__ __forceinline__ void ldsm_x2(uint32_t& r0, uint32_t& r1, uint32_t addr) {
    asm volatile("ldmatrix.sync.aligned.m8n8.x2.shared.b16 {%0,%1}, [%2];"
                 : "=r"(r0), "=r"(r1) : "r"(addr));
}
__device__ __forceinline__ void mma_bf16(float* c, const uint32_t* a, const uint32_t* b) {
    asm volatile("mma.sync.aligned.m16n8k16.row.col.f32.bf16.bf16.f32 "
                 "{%0,%1,%2,%3}, {%4,%5,%6,%7}, {%8,%9}, {%0,%1,%2,%3};"
                 : "+f"(c[0]), "+f"(c[1]), "+f"(c[2]), "+f"(c[3])
                 : "r"(a[0]), "r"(a[1]), "r"(a[2]), "r"(a[3]), "r"(b[0]), "r"(b[1]));
}
#define CP_ASYNC16(dst, src) \
    asm volatile("cp.async.cg.shared.global [%0], [%1], 16;" :: "r"(dst), "l"(src))
#define CP_COMMIT() asm volatile("cp.async.commit_group;" ::: "memory")
#define CP_WAIT(n)  asm volatile("cp.async.wait_group %0;" :: "n"(n) : "memory")
#define PADB 144   // padded row stride (72 bf16): conflict-free ldmatrix, 16B-mult

// ---------------- kernel 0a: fp32 -> bf16 scaled convert ---------------------
__global__ void wcvt_kernel(const float* __restrict__ S, __nv_bfloat16* __restrict__ D,
                            float scale)
{
    int i4 = blockIdx.x * 256 + threadIdx.x;
    float4 v = *(const float4*)&S[(size_t)i4 * 4];
    __nv_bfloat16 o[4] = {__float2bfloat16(v.x*scale), __float2bfloat16(v.y*scale),
                          __float2bfloat16(v.z*scale), __float2bfloat16(v.w*scale)};
    *(uint2*)&D[(size_t)i4 * 4] = *(uint2*)o;
}

// ------- kernel 0b: [B,C,N] fp32 -> [B,N,C] bf16 transpose-convert -----------
__global__ void tcvt_kernel(const float* __restrict__ S, __nv_bfloat16* __restrict__ D)
{
    __shared__ float tile[32][33];
    int n0 = blockIdx.x * 32, c0 = blockIdx.y * 32, b = blockIdx.z;
    int tx = threadIdx.x, ty = threadIdx.y;
    #pragma unroll
    for (int i = ty; i < 32; i += 8)
        tile[i][tx] = S[((size_t)b*Cc + c0 + i)*Nn + n0 + tx];
    __syncthreads();
    #pragma unroll
    for (int i = ty; i < 32; i += 8)
        D[((size_t)b*Nn + n0 + i)*Cc + c0 + tx] = __float2bfloat16(tile[tx][i]);
}

// ---------------- kernel 1: fused multi-scale depthwise conv -----------------
__global__ void conv_kernel(const float* __restrict__ y,
                            const float* __restrict__ w3, const float* __restrict__ b3,
                            const float* __restrict__ w5, const float* __restrict__ b5,
                            const float* __restrict__ w7, const float* __restrict__ b7)
{
    int bc = blockIdx.x;
    int c  = bc & (Cc-1);
    int t  = threadIdx.x;

    __shared__ float tile[38][38];
    __shared__ float wsum[49];
    __shared__ float bias;

    if (t < 49) {
        int dy = t / 7, dx = t % 7;
        float w = w7[c*49 + t];
        if (dy >= 1 && dy <= 5 && dx >= 1 && dx <= 5) w += w5[c*25 + (dy-1)*5 + (dx-1)];
        if (dy >= 2 && dy <= 4 && dx >= 2 && dx <= 4) w += w3[c*9  + (dy-2)*3 + (dx-2)];
        wsum[t] = w;
    }
    if (t == 64) bias = b3[c] + b5[c] + b7[c];

    const float* yp = y + (size_t)bc * Nn;
    for (int i = t; i < 38*38; i += 256) {
        int r  = i / 38 - 3;
        int cl = i % 38 - 3;
        float v = 0.f;
        if (r >= 0 && r < 32 && cl >= 0 && cl < 32) v = yp[r*32 + cl];
        tile[i/38][i%38] = v;
    }
    __syncthreads();

    float* op = g_yf + (size_t)bc * Nn;
    for (int i = t; i < 1024; i += 256) {
        int r = i >> 5, cl = i & 31;
        float acc = bias;
        #pragma unroll
        for (int dy = 0; dy < 7; dy++)
            #pragma unroll
            for (int dx = 0; dx < 7; dx++)
                acc += wsum[dy*7+dx] * tile[r+dy][cl+dx];
        op[i] = acc;
    }
}

// ---------------- kernel 2: layernorm over C per (b,n) -----------------------
__global__ void ln_kernel(const float* __restrict__ lnw, const float* __restrict__ lnb)
{
    int b    = blockIdx.x >> 5;
    int n0   = (blockIdx.x & 31) * 32;
    int lane = threadIdx.x & 31;
    int g    = threadIdx.x >> 5;
    int n    = n0 + lane;

    const float* base = g_yf + (size_t)b*Cc*Nn + n;
    float s = 0.f, s2 = 0.f;
    for (int c = g; c < Cc; c += 8) {
        float v = base[(size_t)c*Nn];
        s += v; s2 += v*v;
    }
    __shared__ float sh[2][8][32];
    sh[0][g][lane] = s; sh[1][g][lane] = s2;
    __syncthreads();
    if (g == 0) {
        float a = 0.f, a2 = 0.f;
        #pragma unroll
        for (int i = 0; i < 8; i++) { a += sh[0][i][lane]; a2 += sh[1][i][lane]; }
        float mu  = a * (1.f/512.f);
        float var = a2 * (1.f/512.f) - mu*mu;
        sh[0][0][lane] = mu;
        sh[1][0][lane] = rsqrtf(var + 1e-5f);
    }
    __syncthreads();
    float mu = sh[0][0][lane], rs = sh[1][0][lane];
    float* ob = g_yn + (size_t)b*Cc*Nn + n;
    for (int c = g; c < Cc; c += 8) {
        float v = base[(size_t)c*Nn];
        ob[(size_t)c*Nn] = (v - mu) * rs * lnw[c] + lnb[c];
    }
}

// ------- kernels 3/4: bf16 mma projection GEMM, double-buffered cp.async -----
#define GM_SMEM (4*128*PADB)
__global__ void __launch_bounds__(256, 2)
gemm_mma_kernel(const __nv_bfloat16* __restrict__ A, const __nv_bfloat16* __restrict__ W,
                __nv_bfloat16* __restrict__ D0, __nv_bfloat16* __restrict__ D1)
{
    extern __shared__ __align__(16) char sm[];
    uint32_t sb = smem_u32(sm);

    int t = threadIdx.x, warp = t >> 5, lane = t & 31;
    int co0 = blockIdx.x * 128, n0 = blockIdx.y * 128, b = blockIdx.z;
    int wn = warp >> 2, wm = warp & 3;

    const char* asrc = (const char*)(A + ((size_t)(b*Nn + n0))*Cc);
    const char* wsrc = (const char*)(W + (size_t)co0*Cc);

    auto issue = [&](int kc, int bi) {
        uint32_t base = sb + bi*(2*128*PADB);
        for (int i = t; i < 1024; i += 256) {
            int row = i >> 3, cb = (i & 7) * 16;
            CP_ASYNC16(base + row*PADB + cb, asrc + (size_t)row*1024 + kc*2 + cb);
            CP_ASYNC16(base + 128*PADB + row*PADB + cb, wsrc + (size_t)row*1024 + kc*2 + cb);
        }
        CP_COMMIT();
    };
    issue(0, 0);

    float acc[4][4][4] = {};
    int lr16 = lane & 15, lh = lane >> 4;
    int l8 = lane & 7,  lq = (lane & 15) >> 3;

    for (int c8 = 0; c8 < 8; c8++) {
        if (c8 < 7) { issue((c8+1)*64, (c8+1)&1); CP_WAIT(1); }
        else        { CP_WAIT(0); }
        __syncthreads();
        uint32_t base = sb + (c8&1)*(2*128*PADB);
        uint32_t aAddr = base + (wn*64 + lr16)*PADB + lh*16;
        uint32_t bAddr = base + 128*PADB + (wm*32 + l8)*PADB + lq*16;
        #pragma unroll
        for (int k0 = 0; k0 < 64; k0 += 16) {
            uint32_t a[4][4], bb[4][2];
            #pragma unroll
            for (int mi = 0; mi < 4; mi++)
                ldsm_x4(a[mi][0], a[mi][1], a[mi][2], a[mi][3],
                        aAddr + mi*16*PADB + k0*2);
            #pragma unroll
            for (int ni = 0; ni < 4; ni++)
                ldsm_x2(bb[ni][0], bb[ni][1], bAddr + ni*8*PADB + k0*2);
            #pragma unroll
            for (int mi = 0; mi < 4; mi++)
                #pragma unroll
                for (int ni = 0; ni < 4; ni++)
                    mma_bf16(acc[mi][ni], a[mi], bb[ni]);
        }
        __syncthreads();
    }

    __nv_bfloat16* D = (co0 < Cc) ? D0 : D1;
    int cadj = (co0 < Cc) ? 0 : Cc;
    int rbase = n0 + wn*64 + (lane >> 2);
    int cbase = co0 - cadj + wm*32 + (lane & 3)*2;
    #pragma unroll
    for (int mi = 0; mi < 4; mi++)
        #pragma unroll
        for (int ni = 0; ni < 4; ni++) {
            float* c = acc[mi][ni];
            size_t r0i = ((size_t)(b*Nn) + rbase + mi*16)*Cc + cbase + ni*8;
            __nv_bfloat162 p0, p1;
            p0.x = __float2bfloat16(c[0]); p0.y = __float2bfloat16(c[1]);
            p1.x = __float2bfloat16(c[2]); p1.y = __float2bfloat16(c[3]);
            *(__nv_bfloat162*)&D[r0i]        = p0;
            *(__nv_bfloat162*)&D[r0i + 8*Cc] = p1;
        }
}

// ---------- kernel 4c: v (bf16) -> transposed bf16 [z][d][m] ------------------
__global__ void split_vt_kernel()
{
    __shared__ __nv_bfloat16 tile[32][33];
    int d0 = blockIdx.x * 32, m0 = blockIdx.y * 32, z = blockIdx.z;
    int b = z >> 3, h = z & 7;
    int tx = threadIdx.x, ty = threadIdx.y;
    #pragma unroll
    for (int i = ty; i < 32; i += 8)
        tile[i][tx] = g_vbf[((size_t)(b*Nn + m0 + i))*Cc + h*64 + d0 + tx];
    __syncthreads();
    #pragma unroll
    for (int i = ty; i < 32; i += 8)
        g_vthi[((size_t)z*64 + d0 + i)*1024 + m0 + tx] = tile[tx][i];
}

// ---------------- kernel 5: QK^T via mma.sync bf16, fp16 logits out ----------
#define QK_SMEM (2*128*PADB)
__global__ void __launch_bounds__(256, 2) qk_mma_kernel()
{
    extern __shared__ __align__(16) char sm[];
    const uint32_t QT = 0, KT = 128*PADB;
    uint32_t sb = smem_u32(sm);

    int t = threadIdx.x, warp = t >> 5, lane = t & 31;
    int m0 = blockIdx.x * 128, n0 = blockIdx.y * 128, z = blockIdx.z;
    int b = z >> 3, h = z & 7;
    int wn = warp >> 2, wm = warp & 3;

    {
        const char* srcs[2] = {
            (const char*)(g_qbf + ((size_t)(b*Nn + n0)*Cc + h*64)),
            (const char*)(g_kbf + ((size_t)(b*Nn + m0)*Cc + h*64))};
        const uint32_t offs[2] = {QT, KT};
        #pragma unroll
        for (int tl = 0; tl < 2; tl++) {
            uint32_t dst = sb + offs[tl];
            for (int i = t; i < 1024; i += 256) {
                int row = i >> 3, cb = (i & 7) * 16;
                CP_ASYNC16(dst + row*PADB + cb, srcs[tl] + (size_t)row*(Cc*2) + cb);
            }
        }
        CP_COMMIT();
        CP_WAIT(0);
    }
    __syncthreads();

    float acc[4][4][4] = {};
    int lr16 = lane & 15, lh = lane >> 4;
    int l8 = lane & 7,  lq = (lane & 15) >> 3;

    uint32_t aAddr = sb + QT + (wn*64 + lr16)*PADB + lh*16;
    uint32_t bAddr = sb + KT + (wm*32 + l8)*PADB + lq*16;
    #pragma unroll
    for (int k0 = 0; k0 < 64; k0 += 16) {
        uint32_t a[4][4], bb[4][2];
        #pragma unroll
        for (int mi = 0; mi < 4; mi++)
            ldsm_x4(a[mi][0], a[mi][1], a[mi][2], a[mi][3],
                    aAddr + mi*16*PADB + k0*2);
        #pragma unroll
        for (int ni = 0; ni < 4; ni++)
            ldsm_x2(bb[ni][0], bb[ni][1], bAddr + ni*8*PADB + k0*2);
        #pragma unroll
        for (int mi = 0; mi < 4; mi++)
            #pragma unroll
            for (int ni = 0; ni < 4; ni++)
                mma_bf16(acc[mi][ni], a[mi], bb[ni]);
    }

    int rbase = n0 + wn*64 + (lane >> 2);
    int cbase = m0 + wm*32 + (lane & 3)*2;
    #pragma unroll
    for (int mi = 0; mi < 4; mi++)
        #pragma unroll
        for (int ni = 0; ni < 4; ni++) {
            float* c = acc[mi][ni];
            __half* A = g_attnh + ((size_t)z*Nn + rbase + mi*16)*Nn + cbase + ni*8;
            *(__half2*)&A[0]           = __floats2half2_rn(c[0], c[1]);
            *(__half2*)&A[(size_t)8*Nn] = __floats2half2_rn(c[2], c[3]);
        }
}

// ---------------- kernel 6: exact top-k on 16-bit keys + dual softmax --------
__device__ __forceinline__ float key2h(unsigned k) {
    unsigned short b = (k & 0x8000u) ? (unsigned short)(k ^ 0x8000u)
                                     : (unsigned short)(~k & 0xFFFFu);
    return __half2float(__ushort_as_half(b));
}

__device__ __forceinline__ unsigned kth_key16(const unsigned* key, int k)
{
    unsigned prefix = 0;
    int kk = k;
    for (int bit = 15; bit >= 0; --bit) {
        unsigned bm = 1u << bit;
        unsigned msk = (bit == 15) ? bm : (((0xFFFFu << (bit+1)) & 0xFFFFu) | bm);
        unsigned want = prefix | bm;
        int c = 0;
        #pragma unroll
        for (int i = 0; i < 32; i++)
            c += ((key[i] & msk) == want) ? 1 : 0;
        c = __reduce_add_sync(0xffffffffu, c);
        if (c == kk) {
            unsigned mn = 0xFFFFu;
            #pragma unroll
            for (int i = 0; i < 32; i++)
                if ((key[i] & msk) == want) mn = min(mn, key[i]);
            return __reduce_min_sync(0xffffffffu, mn);
        } else if (c > kk) {
            prefix |= bm;
        } else {
            kk -= c;
        }
    }
    return prefix;
}

__global__ void select_kernel(const float* __restrict__ kr1, const float* __restrict__ kr2)
{
    int row  = blockIdx.x * 8 + (threadIdx.x >> 5);   // z*1024 + n
    int lane = threadIdx.x & 31;

    float r1 = kr1[0], r2 = kr2[0];
    int k1 = (int)(1024.f * (1.f/(1.f+expf(-r1)))); k1 = min(max(k1,1),1024);
    int k2 = (int)(1024.f * (1.f/(1.f+expf(-r2)))); k2 = min(max(k2,1),1024);

    const __half* rp = g_attnh + (size_t)row * Nn;
    unsigned key[32];
    // vectorized load: chunk i covers halves [i*256, i*256+256), lane gets 8
    #pragma unroll
    for (int i = 0; i < 4; i++) {
        uint4 v = *(const uint4*)(rp + i*256 + lane*8);
        const unsigned short* hh = (const unsigned short*)&v;
        #pragma unroll
        for (int j = 0; j < 8; j++) {
            unsigned b = hh[j];
            key[i*8 + j] = (b & 0x8000u) ? ((~b) & 0xFFFFu) : (b | 0x8000u);
        }
    }

    unsigned mx = 0;
    #pragma unroll
    for (int i = 0; i < 32; i++) mx = max(mx, key[i]);
    mx = __reduce_max_sync(0xffffffffu, mx);
    float M = key2h(mx);

    unsigned T1 = kth_key16(key, k1);
    unsigned T2 = kth_key16(key, k2);

    float ev[32];
    float s1 = 0.f, s2 = 0.f;
    #pragma unroll
    for (int i = 0; i < 32; i++) {
        ev[i] = __expf(key2h(key[i]) - M);
        if (key[i] >= T1) s1 += ev[i];
        if (key[i] >= T2) s2 += ev[i];
    }
    #pragma unroll
    for (int o = 16; o; o >>= 1) {
        s1 += __shfl_xor_sync(0xffffffffu, s1, o);
        s2 += __shfl_xor_sync(0xffffffffu, s2, o);
    }
    float c1 = 0.6f / s1, c2 = 0.4f / s2;
    __nv_bfloat16* ch = g_chi + (size_t)row * Nn;
    #pragma unroll
    for (int i = 0; i < 4; i++) {
        __nv_bfloat16 ob[8];
        #pragma unroll
        for (int j = 0; j < 8; j++) {
            int e = i*8 + j;
            float w = (key[e] >= T1 ? c1 : 0.f) + (key[e] >= T2 ? c2 : 0.f);
            ob[j] = __float2bfloat16(ev[e] * w);
        }
        *(uint4*)(ch + i*256 + lane*8) = *(const uint4*)ob;
    }
}

// ------- kernel 7: AV via mma.sync bf16, double-buffered, bf16 output --------
#define AV_SMEM (2*(192*PADB))
__global__ void __launch_bounds__(256, 2) av_mma_kernel()
{
    extern __shared__ __align__(16) char sm[];
    uint32_t sb = smem_u32(sm);

    int t = threadIdx.x, warp = t >> 5, lane = t & 31;
    int n0 = blockIdx.x * 128, z = blockIdx.y;
    int b = z >> 3, h = z & 7;
    int wn = warp >> 1, wd = warp & 1;

    const char* ch = (const char*)(g_chi  + ((size_t)z*Nn + n0)*Nn);
    const char* vh = (const char*)(g_vthi + (size_t)z*64*1024);

    auto issue = [&](int m0, int bi) {
        uint32_t base = sb + bi*(192*PADB);
        for (int i = t; i < 1024; i += 256) {
            int row = i >> 3, cb = (i & 7) * 16;
            CP_ASYNC16(base + row*PADB + cb, ch + (size_t)row*2048 + m0*2 + cb);
        }
        for (int i = t; i < 512; i += 256) {
            int row = i >> 3, cb = (i & 7) * 16;
            CP_ASYNC16(base + 128*PADB + row*PADB + cb, vh + (size_t)row*2048 + m0*2 + cb);
        }
        CP_COMMIT();
    };
    issue(0, 0);

    float acc[2][4][4] = {};
    int lr16 = lane & 15, lh = lane >> 4;
    int l8 = lane & 7,  lq = (lane & 15) >> 3;

    for (int c16 = 0; c16 < 16; c16++) {
        if (c16 < 15) { issue((c16+1)*64, (c16+1)&1); CP_WAIT(1); }
        else          { CP_WAIT(0); }
        __syncthreads();
        uint32_t base = sb + (c16&1)*(192*PADB);
        uint32_t aAddr = base + (wn*32 + lr16)*PADB + lh*16;
        uint32_t bAddr = base + 128*PADB + (wd*32 + l8)*PADB + lq*16;
        #pragma unroll
        for (int k0 = 0; k0 < 64; k0 += 16) {
            uint32_t a[2][4], bb[4][2];
            #pragma unroll
            for (int mi = 0; mi < 2; mi++)
                ldsm_x4(a[mi][0], a[mi][1], a[mi][2], a[mi][3],
                        aAddr + mi*16*PADB + k0*2);
            #pragma unroll
            for (int ni = 0; ni < 4; ni++)
                ldsm_x2(bb[ni][0], bb[ni][1], bAddr + ni*8*PADB + k0*2);
            #pragma unroll
            for (int mi = 0; mi < 2; mi++)
                #pragma unroll
                for (int ni = 0; ni < 4; ni++)
                    mma_bf16(acc[mi][ni], a[mi], bb[ni]);
        }
        __syncthreads();
    }

    int rbase = n0 + wn*32 + (lane >> 2);
    int cbase = h*64 + wd*32 + (lane & 3)*2;
    #pragma unroll
    for (int mi = 0; mi < 2; mi++)
        #pragma unroll
        for (int ni = 0; ni < 4; ni++) {
            float* c = acc[mi][ni];
            size_t o0 = ((size_t)(b*Nn) + rbase + mi*16)*Cc + cbase + ni*8;
            __nv_bfloat162 p0, p1;
            p0.x = __float2bfloat16(c[0]); p0.y = __float2bfloat16(c[1]);
            p1.x = __float2bfloat16(c[2]); p1.y = __float2bfloat16(c[3]);
            *(__nv_bfloat162*)&g_obf[o0]        = p0;
            *(__nv_bfloat162*)&g_obf[o0 + 8*Cc] = p1;
        }
}

// ------- kernel 8: proj via mma; out[b,c,n] = W.o + bias + x ------------------
#define PJ_SMEM (4*128*PADB)
__global__ void __launch_bounds__(256, 2)
proj_mma_kernel(const float* __restrict__ bias, const float* __restrict__ x,
                float* __restrict__ OUT)
{
    extern __shared__ __align__(16) char sm[];
    uint32_t sb = smem_u32(sm);

    int t = threadIdx.x, warp = t >> 5, lane = t & 31;
    int c0 = blockIdx.x * 128, n0 = blockIdx.y * 128, b = blockIdx.z;
    int wc = warp >> 2, wnn = warp & 3;

    const char* wsrc = (const char*)(g_pwb + (size_t)c0*Cc);
    const char* osrc = (const char*)(g_obf + ((size_t)(b*Nn + n0))*Cc);

    auto issue = [&](int kc, int bi) {
        uint32_t base = sb + bi*(2*128*PADB);
        for (int i = t; i < 1024; i += 256) {
            int row = i >> 3, cb = (i & 7) * 16;
            CP_ASYNC16(base + row*PADB + cb, wsrc + (size_t)row*1024 + kc*2 + cb);
            CP_ASYNC16(base + 128*PADB + row*PADB + cb, osrc + (size_t)row*1024 + kc*2 + cb);
        }
        CP_COMMIT();
    };
    issue(0, 0);

    float acc[4][4][4] = {};
    int lr16 = lane & 15, lh = lane >> 4;
    int l8 = lane & 7,  lq = (lane & 15) >> 3;

    for (int c8 = 0; c8 < 8; c8++) {
        if (c8 < 7) { issue((c8+1)*64, (c8+1)&1); CP_WAIT(1); }
        else        { CP_WAIT(0); }
        __syncthreads();
        uint32_t base = sb + (c8&1)*(2*128*PADB);
        uint32_t aAddr = base + (wc*64 + lr16)*PADB + lh*16;
        uint32_t bAddr = base + 128*PADB + (wnn*32 + l8)*PADB + lq*16;
        #pragma unroll
        for (int k0 = 0; k0 < 64; k0 += 16) {
            uint32_t a[4][4], bb[4][2];
            #pragma unroll
            for (int mi = 0; mi < 4; mi++)
                ldsm_x4(a[mi][0], a[mi][1], a[mi][2], a[mi][3],
                        aAddr + mi*16*PADB + k0*2);
            #pragma unroll
            for (int ni = 0; ni < 4; ni++)
                ldsm_x2(bb[ni][0], bb[ni][1], bAddr + ni*8*PADB + k0*2);
            #pragma unroll
            for (int mi = 0; mi < 4; mi++)
                #pragma unroll
                for (int ni = 0; ni < 4; ni++)
                    mma_bf16(acc[mi][ni], a[mi], bb[ni]);
        }
        __syncthreads();
    }

    int cb0 = c0 + wc*64 + (lane >> 2);
    int nb0 = n0 + wnn*32 + (lane & 3)*2;
    #pragma unroll
    for (int mi = 0; mi < 4; mi++) {
        int c = cb0 + mi*16;
        float bs0 = bias[c], bs8 = bias[c + 8];
        #pragma unroll
        for (int ni = 0; ni < 4; ni++) {
            float* a = acc[mi][ni];
            int n = nb0 + ni*8;
            size_t i0 = ((size_t)b*Cc + c)*Nn + n;
            float2 x0 = *(const float2*)&x[i0];
            *(float2*)&OUT[i0] = make_float2(a[0] + bs0 + x0.x, a[1] + bs0 + x0.y);
            size_t i8 = i0 + (size_t)8*Nn;
            float2 x8 = *(const float2*)&x[i8];
            *(float2*)&OUT[i8] = make_float2(a[2] + bs8 + x8.x, a[3] + bs8 + x8.y);
        }
    }
}

// -----------------------------------------------------------------------------
extern "C" void kernel_launch(void* const* d_in, const int* in_sizes, int n_in,
                              void* d_out, int out_size)
{
    const float* x       = (const float*)d_in[0];
    const float* y       = (const float*)d_in[1];
    const float* q_w     = (const float*)d_in[2];
    const float* kv_w    = (const float*)d_in[3];
    const float* proj_w  = (const float*)d_in[4];
    const float* proj_b  = (const float*)d_in[5];
    const float* conv1_w = (const float*)d_in[6];
    const float* conv1_b = (const float*)d_in[7];
    const float* conv2_w = (const float*)d_in[8];
    const float* conv2_b = (const float*)d_in[9];
    const float* conv3_w = (const float*)d_in[10];
    const float* conv3_b = (const float*)d_in[11];
    const float* ln_w    = (const float*)d_in[12];
    const float* ln_b    = (const float*)d_in[13];
    const float* kr1     = (const float*)d_in[14];
    const float* kr2     = (const float*)d_in[15];
    float* out = (float*)d_out;

    float* yn_p;
    __nv_bfloat16 *xbf, *ynbf, *qwb, *kvwb, *pwb, *qbf, *kbf, *vbf;
    cudaGetSymbolAddress((void**)&yn_p, g_yn);
    cudaGetSymbolAddress((void**)&xbf,  g_xbf);
    cudaGetSymbolAddress((void**)&ynbf, g_ynbf);
    cudaGetSymbolAddress((void**)&qwb,  g_qwb);
    cudaGetSymbolAddress((void**)&kvwb, g_kvwb);
    cudaGetSymbolAddress((void**)&pwb,  g_pwb);
    cudaGetSymbolAddress((void**)&qbf,  g_qbf);
    cudaGetSymbolAddress((void**)&kbf,  g_kbf);
    cudaGetSymbolAddress((void**)&vbf,  g_vbf);

    cudaFuncSetAttribute(gemm_mma_kernel, cudaFuncAttributeMaxDynamicSharedMemorySize, GM_SMEM);
    cudaFuncSetAttribute(qk_mma_kernel,   cudaFuncAttributeMaxDynamicSharedMemorySize, QK_SMEM);
    cudaFuncSetAttribute(av_mma_kernel,   cudaFuncAttributeMaxDynamicSharedMemorySize, AV_SMEM);
    cudaFuncSetAttribute(proj_mma_kernel, cudaFuncAttributeMaxDynamicSharedMemorySize, PJ_SMEM);

    dim3 tb(32, 8);
    wcvt_kernel<<<Cc*Cc/4/256, 256>>>(q_w,    qwb,  0.125f);
    wcvt_kernel<<<2*Cc*Cc/4/256, 256>>>(kv_w, kvwb, 1.f);
    wcvt_kernel<<<Cc*Cc/4/256, 256>>>(proj_w, pwb,  1.f);

    conv_kernel<<<Bz*Cc, 256>>>(y, conv1_w, conv1_b, conv2_w, conv2_b, conv3_w, conv3_b);
    ln_kernel<<<Bz*32, 256>>>(ln_w, ln_b);

    tcvt_kernel<<<dim3(32, 16, Bz), tb>>>(x,    xbf);
    tcvt_kernel<<<dim3(32, 16, Bz), tb>>>(yn_p, ynbf);

    gemm_mma_kernel<<<dim3(4, 8, Bz), 256, GM_SMEM>>>(xbf,  qwb,  qbf, qbf);
    gemm_mma_kernel<<<dim3(8, 8, Bz), 256, GM_SMEM>>>(ynbf, kvwb, kbf, vbf);

    split_vt_kernel<<<dim3(2, 32, 64), tb>>>();

    qk_mma_kernel<<<dim3(Nn/128, Nn/128, Bz*8), 256, QK_SMEM>>>();
    select_kernel<<<Bz*8*Nn/8, 256>>>(kr1, kr2);
    av_mma_kernel<<<dim3(Nn/128, Bz*8), 256, AV_SMEM>>>();
    proj_mma_kernel<<<dim3(Cc/128, Nn/128, Bz), 256, PJ_SMEM>>>(proj_b, x, out);
}

// round 10
// speedup vs baseline: 2.6327x; 1.0327x over previous
#include <cuda_runtime.h>
#include <cuda_bf16.h>
#include <cuda_fp16.h>
#include <cstdint>

#define Bz 8
#define Cc 512
#define Nn 1024

// ---------------- device scratch (no allocations allowed) --------------------
__device__ float g_yf[Bz*Cc*Nn];               // conv output [B,C,N]
__device__ float g_yn[Bz*Cc*Nn];               // layernorm output [B,C,N]
__device__ __half g_attnh[(size_t)64*1024*1024]; // attn [64 z][1024 n][1024 m] fp16
// bf16 operand buffers
__device__ __nv_bfloat16 g_xbf [Bz*Nn*Cc];     // x^T  [b,n,512]
__device__ __nv_bfloat16 g_ynbf[Bz*Nn*Cc];     // yn^T [b,n,512]
__device__ __nv_bfloat16 g_qwb [Cc*Cc];        // 0.125*q_w  [co,512]
__device__ __nv_bfloat16 g_kvwb[2*Cc*Cc];      // kv_w [co,512]
__device__ __nv_bfloat16 g_pwb [Cc*Cc];        // proj_w [co,512]
__device__ __nv_bfloat16 g_qbf [Bz*Nn*Cc];     // q  [b,n,512]
__device__ __nv_bfloat16 g_kbf [Bz*Nn*Cc];     // k  [b,n,512]
__device__ __nv_bfloat16 g_vbf [Bz*Nn*Cc];     // v  [b,n,512]
__device__ __nv_bfloat16 g_obf [Bz*Nn*Cc];     // attn out [b,n,512]
__device__ __nv_bfloat16 g_vthi[(size_t)64*64*1024];   // v^T [z,d,m]
__device__ __nv_bfloat16 g_chi [(size_t)64*1024*1024]; // coeff [z,n,m]

// =================== warp-MMA helpers (plain sm_103-safe PTX) ================
__device__ __forceinline__ uint32_t smem_u32(const void* p) {
    uint32_t a;
    asm("{ .reg .u64 t; cvta.to.shared.u64 t, %1; cvt.u32.u64 %0, t; }"
        : "=r"(a) : "l"(p));
    return a;
}
__device__ __forceinline__ void ldsm_x4(uint32_t& r0, uint32_t& r1, uint32_t& r2,
                                        uint32_t& r3, uint32_t addr) {
    asm volatile("ldmatrix.sync.aligned.m8n8.x4.shared.b16 {%0,%1,%2,%3}, [%4];"
                 : "=r"(r0), "=r"(r1), "=r"(r2), "=r"(r3) : "r"(addr));
}
__device__ __forceinline__ void ldsm_x2(uint32_t& r0, uint32_t& r1, uint32_t addr) {
    asm volatile("ldmatrix.sync.aligned.m8n8.x2.shared.b16 {%0,%1}, [%2];"
                 : "=r"(r0), "=r"(r1) : "r"(addr));
}
__device__ __forceinline__ void mma_bf16(float* c, const uint32_t* a, const uint32_t* b) {
    asm volatile("mma.sync.aligned.m16n8k16.row.col.f32.bf16.bf16.f32 "
                 "{%0,%1,%2,%3}, {%4,%5,%6,%7}, {%8,%9}, {%0,%1,%2,%3};"
                 : "+f"(c[0]), "+f"(c[1]), "+f"(c[2]), "+f"(c[3])
                 : "r"(a[0]), "r"(a[1]), "r"(a[2]), "r"(a[3]), "r"(b[0]), "r"(b[1]));
}
#define CP_ASYNC16(dst, src) \
    asm volatile("cp.async.cg.shared.global [%0], [%1], 16;" :: "r"(dst), "l"(src))
#define CP_COMMIT() asm volatile("cp.async.commit_group;" ::: "memory")
#define CP_WAIT(n)  asm volatile("cp.async.wait_group %0;" :: "n"(n) : "memory")
#define PADB 144   // padded row stride (72 bf16): conflict-free ldmatrix, 16B-mult

// ================= K1: fused conv | weight-convert | x transpose =============
// blocks [0,4096)      : conv (one per b*512+c)
// blocks [4096,5120)   : wcvt (q 256 | kv 512 | proj 256 blocks of 1024 elems)
// blocks [5120,9216)   : tcvt x -> xbf (4096 tiles of 32x32)
#define K1_SMEM (38*40*4 + 64*4)

__device__ void conv_body(int bc, int t,
                          const float* __restrict__ y,
                          const float* __restrict__ w3, const float* __restrict__ b3,
                          const float* __restrict__ w5, const float* __restrict__ b5,
                          const float* __restrict__ w7, const float* __restrict__ b7)
{
    extern __shared__ __align__(16) char k1sm[];
    float* tile  = (float*)k1sm;            // [38][40]
    float* wsum  = tile + 38*40;            // [49]
    float* biasp = wsum + 49;

    int c = bc & (Cc-1);
    if (t < 49) {
        int dy = t / 7, dx = t % 7;
        float w = w7[c*49 + t];
        if (dy >= 1 && dy <= 5 && dx >= 1 && dx <= 5) w += w5[c*25 + (dy-1)*5 + (dx-1)];
        if (dy >= 2 && dy <= 4 && dx >= 2 && dx <= 4) w += w3[c*9  + (dy-2)*3 + (dx-2)];
        wsum[t] = w;
    }
    if (t == 64) *biasp = b3[c] + b5[c] + b7[c];

    const float* yp = y + (size_t)bc * Nn;
    for (int i = t; i < 38*38; i += 256) {
        int rr = i / 38, cc = i % 38;
        int r = rr - 3, cl = cc - 3;
        float v = 0.f;
        if (r >= 0 && r < 32 && cl >= 0 && cl < 32) v = yp[r*32 + cl];
        tile[rr*40 + cc] = v;
    }
    __syncthreads();

    int r  = t >> 3;            // 0..31
    int cq = (t & 7) * 4;       // 0..28
    float bias = *biasp;
    float a0 = bias, a1 = bias, a2 = bias, a3 = bias;
    #pragma unroll
    for (int dy = 0; dy < 7; dy++) {
        float rv[12];
        const float* rp = &tile[(r+dy)*40 + cq];
        *(float4*)&rv[0] = *(const float4*)rp;
        *(float4*)&rv[4] = *(const float4*)(rp + 4);
        *(float4*)&rv[8] = *(const float4*)(rp + 8);
        #pragma unroll
        for (int dx = 0; dx < 7; dx++) {
            float w = wsum[dy*7 + dx];
            a0 += w*rv[dx];   a1 += w*rv[dx+1];
            a2 += w*rv[dx+2]; a3 += w*rv[dx+3];
        }
    }
    *(float4*)&g_yf[(size_t)bc*Nn + r*32 + cq] = make_float4(a0, a1, a2, a3);
}

__device__ void wcvt_body(int b2, int t,
                          const float* __restrict__ q_w,
                          const float* __restrict__ kv_w,
                          const float* __restrict__ proj_w)
{
    const float* S; __nv_bfloat16* D; float scale; int off;
    if (b2 < 256)      { S = q_w;    D = g_qwb;  scale = 0.125f; off = b2; }
    else if (b2 < 768) { S = kv_w;   D = g_kvwb; scale = 1.f;    off = b2 - 256; }
    else               { S = proj_w; D = g_pwb;  scale = 1.f;    off = b2 - 768; }
    int i4 = off * 256 + t;
    float4 v = *(const float4*)&S[(size_t)i4 * 4];
    __nv_bfloat16 o[4] = {__float2bfloat16(v.x*scale), __float2bfloat16(v.y*scale),
                          __float2bfloat16(v.z*scale), __float2bfloat16(v.w*scale)};
    *(uint2*)&D[(size_t)i4 * 4] = *(uint2*)o;
}

__device__ void tcvt_body(int idx, int t, const float* __restrict__ S,
                          __nv_bfloat16* __restrict__ D)
{
    extern __shared__ __align__(16) char k1sm[];
    float* tile = (float*)k1sm;             // [32][33]
    int n0 = (idx & 31) * 32;
    int c0 = ((idx >> 5) & 15) * 32;
    int b  = idx >> 9;
    int tx = t & 31, ty = t >> 5;           // 32 x 8
    #pragma unroll
    for (int i = ty; i < 32; i += 8)
        tile[i*33 + tx] = S[((size_t)b*Cc + c0 + i)*Nn + n0 + tx];
    __syncthreads();
    #pragma unroll
    for (int i = ty; i < 32; i += 8)
        D[((size_t)b*Nn + n0 + i)*Cc + c0 + tx] = __float2bfloat16(tile[tx*33 + i]);
}

__global__ void __launch_bounds__(256)
k1_kernel(const float* __restrict__ y,
          const float* __restrict__ w3, const float* __restrict__ b3,
          const float* __restrict__ w5, const float* __restrict__ b5,
          const float* __restrict__ w7, const float* __restrict__ b7,
          const float* __restrict__ x,
          const float* __restrict__ q_w, const float* __restrict__ kv_w,
          const float* __restrict__ proj_w)
{
    int blk = blockIdx.x, t = threadIdx.x;
    if (blk < 4096)       conv_body(blk, t, y, w3, b3, w5, b5, w7, b7);
    else if (blk < 5120)  wcvt_body(blk - 4096, t, q_w, kv_w, proj_w);
    else                  tcvt_body(blk - 5120, t, x, g_xbf);
}

// ---------------- standalone yn transpose-convert ----------------------------
__global__ void tcvt_yn_kernel()
{
    extern __shared__ __align__(16) char k1sm[];
    tcvt_body(blockIdx.x, threadIdx.x, g_yn, g_ynbf);
}

// ---------------- kernel 2: layernorm over C per (b,n) -----------------------
__global__ void ln_kernel(const float* __restrict__ lnw, const float* __restrict__ lnb)
{
    int b    = blockIdx.x >> 5;
    int n0   = (blockIdx.x & 31) * 32;
    int lane = threadIdx.x & 31;
    int g    = threadIdx.x >> 5;
    int n    = n0 + lane;

    const float* base = g_yf + (size_t)b*Cc*Nn + n;
    float s = 0.f, s2 = 0.f;
    for (int c = g; c < Cc; c += 8) {
        float v = base[(size_t)c*Nn];
        s += v; s2 += v*v;
    }
    __shared__ float sh[2][8][32];
    sh[0][g][lane] = s; sh[1][g][lane] = s2;
    __syncthreads();
    if (g == 0) {
        float a = 0.f, a2 = 0.f;
        #pragma unroll
        for (int i = 0; i < 8; i++) { a += sh[0][i][lane]; a2 += sh[1][i][lane]; }
        float mu  = a * (1.f/512.f);
        float var = a2 * (1.f/512.f) - mu*mu;
        sh[0][0][lane] = mu;
        sh[1][0][lane] = rsqrtf(var + 1e-5f);
    }
    __syncthreads();
    float mu = sh[0][0][lane], rs = sh[1][0][lane];
    float* ob = g_yn + (size_t)b*Cc*Nn + n;
    for (int c = g; c < Cc; c += 8) {
        float v = base[(size_t)c*Nn];
        ob[(size_t)c*Nn] = (v - mu) * rs * lnw[c] + lnb[c];
    }
}

// ------- kernels 3/4: bf16 mma projection GEMM, double-buffered cp.async -----
#define GM_SMEM (4*128*PADB)
__global__ void __launch_bounds__(256, 2)
gemm_mma_kernel(const __nv_bfloat16* __restrict__ A, const __nv_bfloat16* __restrict__ W,
                __nv_bfloat16* __restrict__ D0, __nv_bfloat16* __restrict__ D1)
{
    extern __shared__ __align__(16) char sm[];
    uint32_t sb = smem_u32(sm);

    int t = threadIdx.x, warp = t >> 5, lane = t & 31;
    int co0 = blockIdx.x * 128, n0 = blockIdx.y * 128, b = blockIdx.z;
    int wn = warp >> 2, wm = warp & 3;

    const char* asrc = (const char*)(A + ((size_t)(b*Nn + n0))*Cc);
    const char* wsrc = (const char*)(W + (size_t)co0*Cc);

    auto issue = [&](int kc, int bi) {
        uint32_t base = sb + bi*(2*128*PADB);
        for (int i = t; i < 1024; i += 256) {
            int row = i >> 3, cb = (i & 7) * 16;
            CP_ASYNC16(base + row*PADB + cb, asrc + (size_t)row*1024 + kc*2 + cb);
            CP_ASYNC16(base + 128*PADB + row*PADB + cb, wsrc + (size_t)row*1024 + kc*2 + cb);
        }
        CP_COMMIT();
    };
    issue(0, 0);

    float acc[4][4][4] = {};
    int lr16 = lane & 15, lh = lane >> 4;
    int l8 = lane & 7,  lq = (lane & 15) >> 3;

    for (int c8 = 0; c8 < 8; c8++) {
        if (c8 < 7) { issue((c8+1)*64, (c8+1)&1); CP_WAIT(1); }
        else        { CP_WAIT(0); }
        __syncthreads();
        uint32_t base = sb + (c8&1)*(2*128*PADB);
        uint32_t aAddr = base + (wn*64 + lr16)*PADB + lh*16;
        uint32_t bAddr = base + 128*PADB + (wm*32 + l8)*PADB + lq*16;
        #pragma unroll
        for (int k0 = 0; k0 < 64; k0 += 16) {
            uint32_t a[4][4], bb[4][2];
            #pragma unroll
            for (int mi = 0; mi < 4; mi++)
                ldsm_x4(a[mi][0], a[mi][1], a[mi][2], a[mi][3],
                        aAddr + mi*16*PADB + k0*2);
            #pragma unroll
            for (int ni = 0; ni < 4; ni++)
                ldsm_x2(bb[ni][0], bb[ni][1], bAddr + ni*8*PADB + k0*2);
            #pragma unroll
            for (int mi = 0; mi < 4; mi++)
                #pragma unroll
                for (int ni = 0; ni < 4; ni++)
                    mma_bf16(acc[mi][ni], a[mi], bb[ni]);
        }
        __syncthreads();
    }

    __nv_bfloat16* D = (co0 < Cc) ? D0 : D1;
    int cadj = (co0 < Cc) ? 0 : Cc;
    int rbase = n0 + wn*64 + (lane >> 2);
    int cbase = co0 - cadj + wm*32 + (lane & 3)*2;
    #pragma unroll
    for (int mi = 0; mi < 4; mi++)
        #pragma unroll
        for (int ni = 0; ni < 4; ni++) {
            float* c = acc[mi][ni];
            size_t r0i = ((size_t)(b*Nn) + rbase + mi*16)*Cc + cbase + ni*8;
            __nv_bfloat162 p0, p1;
            p0.x = __float2bfloat16(c[0]); p0.y = __float2bfloat16(c[1]);
            p1.x = __float2bfloat16(c[2]); p1.y = __float2bfloat16(c[3]);
            *(__nv_bfloat162*)&D[r0i]        = p0;
            *(__nv_bfloat162*)&D[r0i + 8*Cc] = p1;
        }
}

// ---------------- kernel 5: QK^T (z<64) fused with v-transpose (z>=64) -------
#define QK_SMEM (2*128*PADB)
__global__ void __launch_bounds__(256, 2) qksplit_kernel()
{
    extern __shared__ __align__(16) char sm[];
    int t = threadIdx.x;

    if (blockIdx.z >= 64) {
        // v transpose: flat id over (2 d-tiles, 32 m-tiles, 64 z)
        int f = blockIdx.x + blockIdx.y*8 + (blockIdx.z - 64)*64;
        int d0 = (f & 1) * 32, m0 = ((f >> 1) & 31) * 32, z = f >> 6;
        int b = z >> 3, h = z & 7;
        __nv_bfloat16* tile = (__nv_bfloat16*)sm;    // [32][33]
        int tx = t & 31, ty = t >> 5;
        #pragma unroll
        for (int i = ty; i < 32; i += 8)
            tile[i*33 + tx] = g_vbf[((size_t)(b*Nn + m0 + i))*Cc + h*64 + d0 + tx];
        __syncthreads();
        #pragma unroll
        for (int i = ty; i < 32; i += 8)
            g_vthi[((size_t)z*64 + d0 + i)*1024 + m0 + tx] = tile[tx*33 + i];
        return;
    }

    const uint32_t QT = 0, KT = 128*PADB;
    uint32_t sb = smem_u32(sm);
    int warp = t >> 5, lane = t & 31;
    int m0 = blockIdx.x * 128, n0 = blockIdx.y * 128, z = blockIdx.z;
    int b = z >> 3, h = z & 7;
    int wn = warp >> 2, wm = warp & 3;

    {
        const char* srcs[2] = {
            (const char*)(g_qbf + ((size_t)(b*Nn + n0)*Cc + h*64)),
            (const char*)(g_kbf + ((size_t)(b*Nn + m0)*Cc + h*64))};
        const uint32_t offs[2] = {QT, KT};
        #pragma unroll
        for (int tl = 0; tl < 2; tl++) {
            uint32_t dst = sb + offs[tl];
            for (int i = t; i < 1024; i += 256) {
                int row = i >> 3, cb = (i & 7) * 16;
                CP_ASYNC16(dst + row*PADB + cb, srcs[tl] + (size_t)row*(Cc*2) + cb);
            }
        }
        CP_COMMIT();
        CP_WAIT(0);
    }
    __syncthreads();

    float acc[4][4][4] = {};
    int lr16 = lane & 15, lh = lane >> 4;
    int l8 = lane & 7,  lq = (lane & 15) >> 3;

    uint32_t aAddr = sb + QT + (wn*64 + lr16)*PADB + lh*16;
    uint32_t bAddr = sb + KT + (wm*32 + l8)*PADB + lq*16;
    #pragma unroll
    for (int k0 = 0; k0 < 64; k0 += 16) {
        uint32_t a[4][4], bb[4][2];
        #pragma unroll
        for (int mi = 0; mi < 4; mi++)
            ldsm_x4(a[mi][0], a[mi][1], a[mi][2], a[mi][3],
                    aAddr + mi*16*PADB + k0*2);
        #pragma unroll
        for (int ni = 0; ni < 4; ni++)
            ldsm_x2(bb[ni][0], bb[ni][1], bAddr + ni*8*PADB + k0*2);
        #pragma unroll
        for (int mi = 0; mi < 4; mi++)
            #pragma unroll
            for (int ni = 0; ni < 4; ni++)
                mma_bf16(acc[mi][ni], a[mi], bb[ni]);
    }

    int rbase = n0 + wn*64 + (lane >> 2);
    int cbase = m0 + wm*32 + (lane & 3)*2;
    #pragma unroll
    for (int mi = 0; mi < 4; mi++)
        #pragma unroll
        for (int ni = 0; ni < 4; ni++) {
            float* c = acc[mi][ni];
            __half* A = g_attnh + ((size_t)z*Nn + rbase + mi*16)*Nn + cbase + ni*8;
            *(__half2*)&A[0]            = __floats2half2_rn(c[0], c[1]);
            *(__half2*)&A[(size_t)8*Nn] = __floats2half2_rn(c[2], c[3]);
        }
}

// ---------------- kernel 6: exact top-k on 16-bit keys + dual softmax --------
__device__ __forceinline__ float key2h(unsigned k) {
    unsigned short b = (k & 0x8000u) ? (unsigned short)(k ^ 0x8000u)
                                     : (unsigned short)(~k & 0xFFFFu);
    return __half2float(__ushort_as_half(b));
}

__device__ __forceinline__ unsigned kth_key16(const unsigned* key, int k)
{
    unsigned prefix = 0;
    int kk = k;
    for (int bit = 15; bit >= 0; --bit) {
        unsigned bm = 1u << bit;
        unsigned msk = (bit == 15) ? bm : (((0xFFFFu << (bit+1)) & 0xFFFFu) | bm);
        unsigned want = prefix | bm;
        int c = 0;
        #pragma unroll
        for (int i = 0; i < 32; i++)
            c += ((key[i] & msk) == want) ? 1 : 0;
        c = __reduce_add_sync(0xffffffffu, c);
        if (c == kk) {
            unsigned mn = 0xFFFFu;
            #pragma unroll
            for (int i = 0; i < 32; i++)
                if ((key[i] & msk) == want) mn = min(mn, key[i]);
            return __reduce_min_sync(0xffffffffu, mn);
        } else if (c > kk) {
            prefix |= bm;
        } else {
            kk -= c;
        }
    }
    return prefix;
}

__global__ void select_kernel(const float* __restrict__ kr1, const float* __restrict__ kr2)
{
    int row  = blockIdx.x * 8 + (threadIdx.x >> 5);   // z*1024 + n
    int lane = threadIdx.x & 31;

    float r1 = kr1[0], r2 = kr2[0];
    int k1 = (int)(1024.f * (1.f/(1.f+expf(-r1)))); k1 = min(max(k1,1),1024);
    int k2 = (int)(1024.f * (1.f/(1.f+expf(-r2)))); k2 = min(max(k2,1),1024);

    const __half* rp = g_attnh + (size_t)row * Nn;
    unsigned key[32];
    #pragma unroll
    for (int i = 0; i < 4; i++) {
        uint4 v = *(const uint4*)(rp + i*256 + lane*8);
        const unsigned short* hh = (const unsigned short*)&v;
        #pragma unroll
        for (int j = 0; j < 8; j++) {
            unsigned b = hh[j];
            key[i*8 + j] = (b & 0x8000u) ? ((~b) & 0xFFFFu) : (b | 0x8000u);
        }
    }

    unsigned mx = 0;
    #pragma unroll
    for (int i = 0; i < 32; i++) mx = max(mx, key[i]);
    mx = __reduce_max_sync(0xffffffffu, mx);
    float M = key2h(mx);

    unsigned T1 = kth_key16(key, k1);
    unsigned T2 = kth_key16(key, k2);

    float ev[32];
    float s1 = 0.f, s2 = 0.f;
    #pragma unroll
    for (int i = 0; i < 32; i++) {
        ev[i] = __expf(key2h(key[i]) - M);
        if (key[i] >= T1) s1 += ev[i];
        if (key[i] >= T2) s2 += ev[i];
    }
    #pragma unroll
    for (int o = 16; o; o >>= 1) {
        s1 += __shfl_xor_sync(0xffffffffu, s1, o);
        s2 += __shfl_xor_sync(0xffffffffu, s2, o);
    }
    float c1 = 0.6f / s1, c2 = 0.4f / s2;
    __nv_bfloat16* ch = g_chi + (size_t)row * Nn;
    #pragma unroll
    for (int i = 0; i < 4; i++) {
        __nv_bfloat16 ob[8];
        #pragma unroll
        for (int j = 0; j < 8; j++) {
            int e = i*8 + j;
            float w = (key[e] >= T1 ? c1 : 0.f) + (key[e] >= T2 ? c2 : 0.f);
            ob[j] = __float2bfloat16(ev[e] * w);
        }
        *(uint4*)(ch + i*256 + lane*8) = *(const uint4*)ob;
    }
}

// ------- kernel 7: AV via mma.sync bf16, double-buffered, bf16 output --------
#define AV_SMEM (2*(192*PADB))
__global__ void __launch_bounds__(256, 2) av_mma_kernel()
{
    extern __shared__ __align__(16) char sm[];
    uint32_t sb = smem_u32(sm);

    int t = threadIdx.x, warp = t >> 5, lane = t & 31;
    int n0 = blockIdx.x * 128, z = blockIdx.y;
    int b = z >> 3, h = z & 7;
    int wn = warp >> 1, wd = warp & 1;

    const char* ch = (const char*)(g_chi  + ((size_t)z*Nn + n0)*Nn);
    const char* vh = (const char*)(g_vthi + (size_t)z*64*1024);

    auto issue = [&](int m0, int bi) {
        uint32_t base = sb + bi*(192*PADB);
        for (int i = t; i < 1024; i += 256) {
            int row = i >> 3, cb = (i & 7) * 16;
            CP_ASYNC16(base + row*PADB + cb, ch + (size_t)row*2048 + m0*2 + cb);
        }
        for (int i = t; i < 512; i += 256) {
            int row = i >> 3, cb = (i & 7) * 16;
            CP_ASYNC16(base + 128*PADB + row*PADB + cb, vh + (size_t)row*2048 + m0*2 + cb);
        }
        CP_COMMIT();
    };
    issue(0, 0);

    float acc[2][4][4] = {};
    int lr16 = lane & 15, lh = lane >> 4;
    int l8 = lane & 7,  lq = (lane & 15) >> 3;

    for (int c16 = 0; c16 < 16; c16++) {
        if (c16 < 15) { issue((c16+1)*64, (c16+1)&1); CP_WAIT(1); }
        else          { CP_WAIT(0); }
        __syncthreads();
        uint32_t base = sb + (c16&1)*(192*PADB);
        uint32_t aAddr = base + (wn*32 + lr16)*PADB + lh*16;
        uint32_t bAddr = base + 128*PADB + (wd*32 + l8)*PADB + lq*16;
        #pragma unroll
        for (int k0 = 0; k0 < 64; k0 += 16) {
            uint32_t a[2][4], bb[4][2];
            #pragma unroll
            for (int mi = 0; mi < 2; mi++)
                ldsm_x4(a[mi][0], a[mi][1], a[mi][2], a[mi][3],
                        aAddr + mi*16*PADB + k0*2);
            #pragma unroll
            for (int ni = 0; ni < 4; ni++)
                ldsm_x2(bb[ni][0], bb[ni][1], bAddr + ni*8*PADB + k0*2);
            #pragma unroll
            for (int mi = 0; mi < 2; mi++)
                #pragma unroll
                for (int ni = 0; ni < 4; ni++)
                    mma_bf16(acc[mi][ni], a[mi], bb[ni]);
        }
        __syncthreads();
    }

    int rbase = n0 + wn*32 + (lane >> 2);
    int cbase = h*64 + wd*32 + (lane & 3)*2;
    #pragma unroll
    for (int mi = 0; mi < 2; mi++)
        #pragma unroll
        for (int ni = 0; ni < 4; ni++) {
            float* c = acc[mi][ni];
            size_t o0 = ((size_t)(b*Nn) + rbase + mi*16)*Cc + cbase + ni*8;
            __nv_bfloat162 p0, p1;
            p0.x = __float2bfloat16(c[0]); p0.y = __float2bfloat16(c[1]);
            p1.x = __float2bfloat16(c[2]); p1.y = __float2bfloat16(c[3]);
            *(__nv_bfloat162*)&g_obf[o0]        = p0;
            *(__nv_bfloat162*)&g_obf[o0 + 8*Cc] = p1;
        }
}

// ------- kernel 8: proj via mma; out[b,c,n] = W.o + bias + x ------------------
#define PJ_SMEM (4*128*PADB)
__global__ void __launch_bounds__(256, 2)
proj_mma_kernel(const float* __restrict__ bias, const float* __restrict__ x,
                float* __restrict__ OUT)
{
    extern __shared__ __align__(16) char sm[];
    uint32_t sb = smem_u32(sm);

    int t = threadIdx.x, warp = t >> 5, lane = t & 31;
    int c0 = blockIdx.x * 128, n0 = blockIdx.y * 128, b = blockIdx.z;
    int wc = warp >> 2, wnn = warp & 3;

    const char* wsrc = (const char*)(g_pwb + (size_t)c0*Cc);
    const char* osrc = (const char*)(g_obf + ((size_t)(b*Nn + n0))*Cc);

    auto issue = [&](int kc, int bi) {
        uint32_t base = sb + bi*(2*128*PADB);
        for (int i = t; i < 1024; i += 256) {
            int row = i >> 3, cb = (i & 7) * 16;
            CP_ASYNC16(base + row*PADB + cb, wsrc + (size_t)row*1024 + kc*2 + cb);
            CP_ASYNC16(base + 128*PADB + row*PADB + cb, osrc + (size_t)row*1024 + kc*2 + cb);
        }
        CP_COMMIT();
    };
    issue(0, 0);

    float acc[4][4][4] = {};
    int lr16 = lane & 15, lh = lane >> 4;
    int l8 = lane & 7,  lq = (lane & 15) >> 3;

    for (int c8 = 0; c8 < 8; c8++) {
        if (c8 < 7) { issue((c8+1)*64, (c8+1)&1); CP_WAIT(1); }
        else        { CP_WAIT(0); }
        __syncthreads();
        uint32_t base = sb + (c8&1)*(2*128*PADB);
        uint32_t aAddr = base + (wc*64 + lr16)*PADB + lh*16;
        uint32_t bAddr = base + 128*PADB + (wnn*32 + l8)*PADB + lq*16;
        #pragma unroll
        for (int k0 = 0; k0 < 64; k0 += 16) {
            uint32_t a[4][4], bb[4][2];
            #pragma unroll
            for (int mi = 0; mi < 4; mi++)
                ldsm_x4(a[mi][0], a[mi][1], a[mi][2], a[mi][3],
                        aAddr + mi*16*PADB + k0*2);
            #pragma unroll
            for (int ni = 0; ni < 4; ni++)
                ldsm_x2(bb[ni][0], bb[ni][1], bAddr + ni*8*PADB + k0*2);
            #pragma unroll
            for (int mi = 0; mi < 4; mi++)
                #pragma unroll
                for (int ni = 0; ni < 4; ni++)
                    mma_bf16(acc[mi][ni], a[mi], bb[ni]);
        }
        __syncthreads();
    }

    int cb0 = c0 + wc*64 + (lane >> 2);
    int nb0 = n0 + wnn*32 + (lane & 3)*2;
    #pragma unroll
    for (int mi = 0; mi < 4; mi++) {
        int c = cb0 + mi*16;
        float bs0 = bias[c], bs8 = bias[c + 8];
        #pragma unroll
        for (int ni = 0; ni < 4; ni++) {
            float* a = acc[mi][ni];
            int n = nb0 + ni*8;
            size_t i0 = ((size_t)b*Cc + c)*Nn + n;
            float2 x0 = *(const float2*)&x[i0];
            *(float2*)&OUT[i0] = make_float2(a[0] + bs0 + x0.x, a[1] + bs0 + x0.y);
            size_t i8 = i0 + (size_t)8*Nn;
            float2 x8 = *(const float2*)&x[i8];
            *(float2*)&OUT[i8] = make_float2(a[2] + bs8 + x8.x, a[3] + bs8 + x8.y);
        }
    }
}

// -----------------------------------------------------------------------------
extern "C" void kernel_launch(void* const* d_in, const int* in_sizes, int n_in,
                              void* d_out, int out_size)
{
    const float* x       = (const float*)d_in[0];
    const float* y       = (const float*)d_in[1];
    const float* q_w     = (const float*)d_in[2];
    const float* kv_w    = (const float*)d_in[3];
    const float* proj_w  = (const float*)d_in[4];
    const float* proj_b  = (const float*)d_in[5];
    const float* conv1_w = (const float*)d_in[6];
    const float* conv1_b = (const float*)d_in[7];
    const float* conv2_w = (const float*)d_in[8];
    const float* conv2_b = (const float*)d_in[9];
    const float* conv3_w = (const float*)d_in[10];
    const float* conv3_b = (const float*)d_in[11];
    const float* ln_w    = (const float*)d_in[12];
    const float* ln_b    = (const float*)d_in[13];
    const float* kr1     = (const float*)d_in[14];
    const float* kr2     = (const float*)d_in[15];
    float* out = (float*)d_out;

    __nv_bfloat16 *xbf, *ynbf, *qwb, *kvwb, *qbf, *kbf, *vbf;
    cudaGetSymbolAddress((void**)&xbf,  g_xbf);
    cudaGetSymbolAddress((void**)&ynbf, g_ynbf);
    cudaGetSymbolAddress((void**)&qwb,  g_qwb);
    cudaGetSymbolAddress((void**)&kvwb, g_kvwb);
    cudaGetSymbolAddress((void**)&qbf,  g_qbf);
    cudaGetSymbolAddress((void**)&kbf,  g_kbf);
    cudaGetSymbolAddress((void**)&vbf,  g_vbf);

    cudaFuncSetAttribute(gemm_mma_kernel, cudaFuncAttributeMaxDynamicSharedMemorySize, GM_SMEM);
    cudaFuncSetAttribute(qksplit_kernel,  cudaFuncAttributeMaxDynamicSharedMemorySize, QK_SMEM);
    cudaFuncSetAttribute(av_mma_kernel,   cudaFuncAttributeMaxDynamicSharedMemorySize, AV_SMEM);
    cudaFuncSetAttribute(proj_mma_kernel, cudaFuncAttributeMaxDynamicSharedMemorySize, PJ_SMEM);

    // K1: conv | weight-cvt | x transpose-cvt (all independent)
    k1_kernel<<<4096 + 1024 + 4096, 256, K1_SMEM>>>(
        y, conv1_w, conv1_b, conv2_w, conv2_b, conv3_w, conv3_b,
        x, q_w, kv_w, proj_w);

    ln_kernel<<<Bz*32, 256>>>(ln_w, ln_b);

    gemm_mma_kernel<<<dim3(4, 8, Bz), 256, GM_SMEM>>>(xbf, qwb, qbf, qbf);

    tcvt_yn_kernel<<<4096, 256, K1_SMEM>>>();

    gemm_mma_kernel<<<dim3(8, 8, Bz), 256, GM_SMEM>>>(ynbf, kvwb, kbf, vbf);

    // qk (z<64) fused with v-transpose (z>=64)
    qksplit_kernel<<<dim3(8, 8, 128), 256, QK_SMEM>>>();

    select_kernel<<<Bz*8*Nn/8, 256>>>(kr1, kr2);
    av_mma_kernel<<<dim3(Nn/128, Bz*8), 256, AV_SMEM>>>();
    proj_mma_kernel<<<dim3(Cc/128, Nn/128, Bz), 256, PJ_SMEM>>>(proj_b, x, out);
}